// round 9
// baseline (speedup 1.0000x reference)
#include <cuda_runtime.h>
#include <math.h>

#define BB 32
#define CC 64
#define TT_ 128
#define VV 25
#define RR 8
#define TS 9
#define OUTC 64
#define TV 3200   // TT_*VV

typedef unsigned long long u64;

// scratch (allocation-free rule: device globals)
__device__ float g_xm[BB * CC * VV];                 // mean_t x
__device__ float g_dbuf[BB * RR * VV * VV];          // d[b,r,j,i]
__device__ float g_zbuf[(size_t)BB * CC * TT_ * VV]; // z[b,c,t,i]

__device__ __forceinline__ u64 pack2(float lo, float hi) {
    u64 r;
    asm("mov.b64 %0, {%1, %2};" : "=l"(r) : "f"(lo), "f"(hi));
    return r;
}
__device__ __forceinline__ void ffma2(u64& d, u64 a, u64 b) {
    asm("fma.rn.f32x2 %0, %1, %2, %0;" : "+l"(d) : "l"(a), "l"(b));
}
__device__ __forceinline__ float lo32(u64 v) { float a,b; asm("mov.b64 {%0,%1}, %2;" : "=f"(a), "=f"(b) : "l"(v)); return a; }
__device__ __forceinline__ float hi32(u64 v) { float a,b; asm("mov.b64 {%0,%1}, %2;" : "=f"(a), "=f"(b) : "l"(v)); return b; }

// ---------------- kA1: coalesced mean over T, one block per (b,c) ----------------
__global__ void __launch_bounds__(128) kA1(const float* __restrict__ x) {
    int c = blockIdx.x, b = blockIdx.y;
    int tid = threadIdx.x;
    __shared__ float xt[TT_ * VV];
    __shared__ float part[VV * 4];

    const float* xp = x + (size_t)(b * CC + c) * TV;
    for (int i = tid; i < TT_ * VV; i += 128) xt[i] = xp[i];
    __syncthreads();

    if (tid < VV * 4) {
        int v = tid >> 2, s = tid & 3;
        float acc = 0.f;
#pragma unroll 8
        for (int t = s; t < TT_; t += 4) acc += xt[t * VV + v];
        part[tid] = acc;
    }
    __syncthreads();
    if (tid < VV) {
        float m = (part[tid * 4] + part[tid * 4 + 1] + part[tid * 4 + 2] + part[tid * 4 + 3]) * (1.f / (float)TT_);
        g_xm[(b * CC + c) * VV + tid] = m;
    }
}

// ---------------- kA2: x1/x2 + d = tanh(x1-x2), one block per (r, b) ----------------
__global__ void __launch_bounds__(128) kA2(const float* __restrict__ w1, const float* __restrict__ b1,
                                           const float* __restrict__ w2, const float* __restrict__ b2) {
    int r = blockIdx.x;   // 0..7
    int b = blockIdx.y;   // 0..31
    int tid = threadIdx.x;
    __shared__ float xm[CC * VV];
    __shared__ float x1s[VV];
    __shared__ float x2s[VV];

    const float* xmg = g_xm + b * (CC * VV);
    for (int i = tid; i < CC * VV; i += 128) xm[i] = xmg[i];
    __syncthreads();

    if (tid < 2 * VV) {
        int which = tid / VV;
        int v = tid % VV;
        const float* w = which ? w2 : w1;
        float s = 0.f;
#pragma unroll 8
        for (int c = 0; c < CC; c++) s = fmaf(w[r * CC + c], xm[c * VV + v], s);
        s += (which ? b2 : b1)[r];
        (which ? x2s : x1s)[v] = s;
    }
    __syncthreads();

    float* db = g_dbuf + (b * RR + r) * (VV * VV);
    for (int p = tid; p < VV * VV; p += 128) {
        int j = p / VV, i = p % VV;
        db[p] = tanhf(x1s[j] - x2s[i]);
    }
}

// ---------------- kB: dynamic conv, plain W (per-lane LDS.32 + MOV dup) ----------------
// 256 threads (8 warps), warp w owns t in [w*16, w*16+16). lane<25 owns vertex i.
__global__ void __launch_bounds__(256, 3) kB(const float* __restrict__ x,
                                             const float* __restrict__ A,
                                             const float* __restrict__ w4, const float* __restrict__ b4) {
    int c = blockIdx.x;
    int b = blockIdx.y;
    int tid = threadIdx.x;

    __shared__ __align__(16) float Ws[VV * TS * VV];    // [j][k][i] plain, 22.5KB
    __shared__ __align__(16) float xsT[VV * 140];       // [j][s] = xpad[s],   14KB
    __shared__ __align__(16) float xsS[VV * 140];       // [j][s] = xpad[s+1], 14KB

    const float* db = g_dbuf + b * (RR * VV * VV);

    // W[j,i,k] = A[j,i] + b4[c*9+k] + sum_r w4[c*9+k, r] * d[r,j,i]
    for (int p = tid; p < VV * VV; p += 256) {
        float dr[RR];
#pragma unroll
        for (int r = 0; r < RR; r++) dr[r] = __ldg(db + r * (VV * VV) + p);
        float a = __ldg(A + p);
        int j = p / VV, i = p % VV;
#pragma unroll
        for (int k = 0; k < TS; k++) {
            int o = c * TS + k;
            float s = a + __ldg(b4 + o);
#pragma unroll
            for (int r = 0; r < RR; r++) s = fmaf(__ldg(w4 + o * RR + r), dr[r], s);
            Ws[(j * TS + k) * VV + i] = s;
        }
    }

    // stage x: xsT[j][8+t] = x[t][j] (zeros on [0,8) and [136,140));
    //          xsS[j][7+t] = x[t][j] (zeros on [0,7) and [135,140)).
    for (int idx = tid; idx < VV * 8; idx += 256) {
        int j = idx / 8, s0 = idx % 8;
        xsT[j * 140 + s0] = 0.f;
        if (s0 < 7) xsS[j * 140 + s0] = 0.f;
        if (s0 == 0) {
            xsS[j * 140 + 135] = 0.f;
#pragma unroll
            for (int q = 136; q < 140; q++) { xsT[j * 140 + q] = 0.f; xsS[j * 140 + q] = 0.f; }
        }
    }
    const float* xp = x + (size_t)(b * CC + c) * TV;
    for (int idx = tid; idx < TT_ * VV; idx += 256) {
        int t = idx / VV, j = idx % VV;
        float v = xp[idx];
        xsT[j * 140 + t + 8] = v;
        xsS[j * 140 + t + 7] = v;
    }
    __syncthreads();

    int warp = tid >> 5, lane = tid & 31;
    int t0 = warp * 16;

    if (lane < VV) {
        u64 acc[8];
#pragma unroll
        for (int p = 0; p < 8; p++) acc[p] = 0ULL;

        const float* wbase = Ws + lane;

        for (int j = 0; j < VV; j++) {
            u64 pe[12], po[12];
            const ulonglong2* xe = reinterpret_cast<const ulonglong2*>(&xsT[j * 140 + t0]);
            const ulonglong2* xo = reinterpret_cast<const ulonglong2*>(&xsS[j * 140 + t0]);
#pragma unroll
            for (int q = 0; q < 6; q++) {
                ulonglong2 ve = xe[q]; pe[2 * q] = ve.x; pe[2 * q + 1] = ve.y;
                ulonglong2 vo = xo[q]; po[2 * q] = vo.x; po[2 * q + 1] = vo.y;
            }
            const float* wrow = wbase + (j * TS) * VV;
#pragma unroll
            for (int k = 0; k < TS; k++) {
                float w = wrow[k * VV];                 // per-lane LDS.32 (1 wavefront)
                u64 w2 = pack2(w, w);                   // 1 MOV (alu pipe)
                const u64* pr = (k & 1) ? &po[(k - 1) >> 1] : &pe[k >> 1];
#pragma unroll
                for (int p = 0; p < 8; p++) ffma2(acc[p], pr[p], w2);
            }
        }
        float* zp = g_zbuf + (size_t)(b * CC + c) * TV + lane;
#pragma unroll
        for (int p = 0; p < 8; p++) {
            zp[(t0 + 2 * p) * VV] = lo32(acc[p]);
            zp[(t0 + 2 * p + 1) * VV] = hi32(acc[p]);
        }
    }
}

// ---------------- kC: out = w3 @ z + b3, 16o x 4tv per warp ----------------
// block = 128 threads (4 warps). warp <-> 16 o (o0 = warp*16), lane <-> 4 tv.
// Packing is over o-pairs -> weights must be NATURAL pairs (w3T plain, broadcast
// LDS.128 x4 per c), x duplicated via MOV (alu pipe). FIX of R8's dup-side error.
__global__ void __launch_bounds__(128, 3) kC(const float* __restrict__ w3, const float* __restrict__ b3,
                                             float* __restrict__ out) {
    int b = blockIdx.y;
    int tv0 = blockIdx.x * 128;
    int tid = threadIdx.x;
    int warp = tid >> 5, lane = tid & 31;

    __shared__ __align__(16) float zs[CC * 128];    // 32KB, [c][tv] plain
    __shared__ __align__(16) float w3T[CC * OUTC];  // 16KB, [c][o] plain

    const float* zb = g_zbuf + (size_t)b * CC * TV + tv0;
    for (int i = tid; i < CC * 32; i += 128) {
        int c = i >> 5, q = i & 31;
        *reinterpret_cast<float4*>(&zs[c * 128 + q * 4]) =
            *reinterpret_cast<const float4*>(zb + c * TV + q * 4);
    }
    for (int i = tid; i < CC * OUTC; i += 128) {
        int o = i >> 6, c = i & 63;                  // read w3 coalesced [o][c]
        w3T[c * OUTC + o] = w3[i];
    }
    __syncthreads();

    int o0 = warp * 16;
    u64 acc[8][4];   // acc[op][q] packs outputs (o0+2op, o0+2op+1) at tv = lane*4+q
#pragma unroll
    for (int op = 0; op < 8; op++) {
        u64 bp = pack2(__ldg(b3 + o0 + 2 * op), __ldg(b3 + o0 + 2 * op + 1));
#pragma unroll
        for (int q = 0; q < 4; q++) acc[op][q] = bp;
    }

    const float* zrow = &zs[lane * 4];
#pragma unroll 2
    for (int c = 0; c < CC; c++) {
        float4 xv = *reinterpret_cast<const float4*>(zrow + c * 128);   // per-lane LDS.128
        u64 xd0 = pack2(xv.x, xv.x);
        u64 xd1 = pack2(xv.y, xv.y);
        u64 xd2 = pack2(xv.z, xv.z);
        u64 xd3 = pack2(xv.w, xv.w);
        // 16 plain weights = 4 broadcast LDS.128, natural u64 pairs
        const ulonglong2* wrow = reinterpret_cast<const ulonglong2*>(&w3T[c * OUTC + o0]);
#pragma unroll
        for (int h = 0; h < 4; h++) {
            ulonglong2 wp = wrow[h];   // wp.x = (w[o0+4h],w[o0+4h+1]); wp.y = (w[o0+4h+2],w[o0+4h+3])
            ffma2(acc[2 * h][0], xd0, wp.x); ffma2(acc[2 * h][1], xd1, wp.x);
            ffma2(acc[2 * h][2], xd2, wp.x); ffma2(acc[2 * h][3], xd3, wp.x);
            ffma2(acc[2 * h + 1][0], xd0, wp.y); ffma2(acc[2 * h + 1][1], xd1, wp.y);
            ffma2(acc[2 * h + 1][2], xd2, wp.y); ffma2(acc[2 * h + 1][3], xd3, wp.y);
        }
    }

    float* ob = out + (size_t)b * OUTC * TV + tv0 + lane * 4;
#pragma unroll
    for (int op = 0; op < 8; op++) {
        float4 lo, hi;
        lo.x = lo32(acc[op][0]); lo.y = lo32(acc[op][1]);
        lo.z = lo32(acc[op][2]); lo.w = lo32(acc[op][3]);
        hi.x = hi32(acc[op][0]); hi.y = hi32(acc[op][1]);
        hi.z = hi32(acc[op][2]); hi.w = hi32(acc[op][3]);
        *reinterpret_cast<float4*>(ob + (size_t)(o0 + 2 * op) * TV) = lo;
        *reinterpret_cast<float4*>(ob + (size_t)(o0 + 2 * op + 1) * TV) = hi;
    }
}

extern "C" void kernel_launch(void* const* d_in, const int* in_sizes, int n_in,
                              void* d_out, int out_size) {
    const float* x  = (const float*)d_in[0];
    const float* A  = (const float*)d_in[1];
    const float* w1 = (const float*)d_in[2];
    const float* b1 = (const float*)d_in[3];
    const float* w2 = (const float*)d_in[4];
    const float* b2 = (const float*)d_in[5];
    const float* w3 = (const float*)d_in[6];
    const float* b3 = (const float*)d_in[7];
    const float* w4 = (const float*)d_in[8];
    const float* b4 = (const float*)d_in[9];
    float* out = (float*)d_out;

    kA1<<<dim3(CC, BB), 128>>>(x);
    kA2<<<dim3(RR, BB), 128>>>(w1, b1, w2, b2);
    kB<<<dim3(CC, BB), 256>>>(x, A, w4, b4);
    kC<<<dim3(TV / 128, BB), 128>>>(w3, b3, out);
}

// round 10
// speedup vs baseline: 1.0150x; 1.0150x over previous
#include <cuda_runtime.h>
#include <math.h>

#define BB 32
#define CC 64
#define TT_ 128
#define VV 25
#define RR 8
#define TS 9
#define OUTC 64
#define TV 3200   // TT_*VV

typedef unsigned long long u64;

// scratch (allocation-free rule: device globals)
__device__ float g_xm[BB * CC * VV];                 // mean_t x
__device__ float g_dbuf[BB * RR * VV * VV];          // d[b,r,j,i]
__device__ float g_zbuf[(size_t)BB * CC * TT_ * VV]; // z[b,c,t,i]

__device__ __forceinline__ u64 pack2(float lo, float hi) {
    u64 r;
    asm("mov.b64 %0, {%1, %2};" : "=l"(r) : "f"(lo), "f"(hi));
    return r;
}
__device__ __forceinline__ void ffma2(u64& d, u64 a, u64 b) {
    asm("fma.rn.f32x2 %0, %1, %2, %0;" : "+l"(d) : "l"(a), "l"(b));
}
__device__ __forceinline__ float lo32(u64 v) { float a,b; asm("mov.b64 {%0,%1}, %2;" : "=f"(a), "=f"(b) : "l"(v)); return a; }
__device__ __forceinline__ float hi32(u64 v) { float a,b; asm("mov.b64 {%0,%1}, %2;" : "=f"(a), "=f"(b) : "l"(v)); return b; }

// ---------------- kA1: coalesced mean over T, one block per (b,c) ----------------
__global__ void __launch_bounds__(128) kA1(const float* __restrict__ x) {
    int c = blockIdx.x, b = blockIdx.y;
    int tid = threadIdx.x;
    __shared__ float xt[TT_ * VV];
    __shared__ float part[VV * 4];

    const float* xp = x + (size_t)(b * CC + c) * TV;
    for (int i = tid; i < TT_ * VV; i += 128) xt[i] = xp[i];
    __syncthreads();

    if (tid < VV * 4) {
        int v = tid >> 2, s = tid & 3;
        float acc = 0.f;
#pragma unroll 8
        for (int t = s; t < TT_; t += 4) acc += xt[t * VV + v];
        part[tid] = acc;
    }
    __syncthreads();
    if (tid < VV) {
        float m = (part[tid * 4] + part[tid * 4 + 1] + part[tid * 4 + 2] + part[tid * 4 + 3]) * (1.f / (float)TT_);
        g_xm[(b * CC + c) * VV + tid] = m;
    }
}

// ---------------- kA2: x1/x2 + d = tanh(x1-x2), one block per (r, b) ----------------
__global__ void __launch_bounds__(128) kA2(const float* __restrict__ w1, const float* __restrict__ b1,
                                           const float* __restrict__ w2, const float* __restrict__ b2) {
    int r = blockIdx.x;   // 0..7
    int b = blockIdx.y;   // 0..31
    int tid = threadIdx.x;
    __shared__ float xm[CC * VV];
    __shared__ float x1s[VV];
    __shared__ float x2s[VV];

    const float* xmg = g_xm + b * (CC * VV);
    for (int i = tid; i < CC * VV; i += 128) xm[i] = xmg[i];
    __syncthreads();

    if (tid < 2 * VV) {
        int which = tid / VV;
        int v = tid % VV;
        const float* w = which ? w2 : w1;
        float s = 0.f;
#pragma unroll 8
        for (int c = 0; c < CC; c++) s = fmaf(w[r * CC + c], xm[c * VV + v], s);
        s += (which ? b2 : b1)[r];
        (which ? x2s : x1s)[v] = s;
    }
    __syncthreads();

    float* db = g_dbuf + (b * RR + r) * (VV * VV);
    for (int p = tid; p < VV * VV; p += 128) {
        int j = p / VV, i = p % VV;
        db[p] = tanhf(x1s[j] - x2s[i]);
    }
}

// ---------------- kB: dynamic conv, sliding 16-u64 window, low-reg version ----------------
// 256 threads (8 warps), warp w owns t in [w*16, w*16+16). lane<25 owns vertex i.
// Two half-passes over k per j (accs 0..3 then 4..7) so the live x-window stays
// at 16 u64 (32 regs) instead of 48 regs -> no spills, 4 CTAs/SM.
__global__ void __launch_bounds__(256, 4) kB(const float* __restrict__ x,
                                             const float* __restrict__ A,
                                             const float* __restrict__ w4, const float* __restrict__ b4) {
    int c = blockIdx.x;
    int b = blockIdx.y;
    int tid = threadIdx.x;

    __shared__ __align__(16) float Ws[VV * TS * VV];    // [j][k][i] plain, 22.5KB
    __shared__ __align__(16) float xsT[VV * 140];       // [j][s] = xpad[s],   14KB
    __shared__ __align__(16) float xsS[VV * 140];       // [j][s] = xpad[s+1], 14KB

    const float* db = g_dbuf + b * (RR * VV * VV);

    // W[j,i,k] = A[j,i] + b4[c*9+k] + sum_r w4[c*9+k, r] * d[r,j,i]
    for (int p = tid; p < VV * VV; p += 256) {
        float dr[RR];
#pragma unroll
        for (int r = 0; r < RR; r++) dr[r] = __ldg(db + r * (VV * VV) + p);
        float a = __ldg(A + p);
        int j = p / VV, i = p % VV;
#pragma unroll
        for (int k = 0; k < TS; k++) {
            int o = c * TS + k;
            float s = a + __ldg(b4 + o);
#pragma unroll
            for (int r = 0; r < RR; r++) s = fmaf(__ldg(w4 + o * RR + r), dr[r], s);
            Ws[(j * TS + k) * VV + i] = s;
        }
    }

    // stage x: xsT[j][8+t] = x[t][j] (zeros on [0,8) and [136,140));
    //          xsS[j][7+t] = x[t][j] (zeros on [0,7) and [135,140)).
    for (int idx = tid; idx < VV * 8; idx += 256) {
        int j = idx / 8, s0 = idx % 8;
        xsT[j * 140 + s0] = 0.f;
        if (s0 < 7) xsS[j * 140 + s0] = 0.f;
        if (s0 == 0) {
            xsS[j * 140 + 135] = 0.f;
#pragma unroll
            for (int q = 136; q < 140; q++) { xsT[j * 140 + q] = 0.f; xsS[j * 140 + q] = 0.f; }
        }
    }
    const float* xp = x + (size_t)(b * CC + c) * TV;
    for (int idx = tid; idx < TT_ * VV; idx += 256) {
        int t = idx / VV, j = idx % VV;
        float v = xp[idx];
        xsT[j * 140 + t + 8] = v;
        xsS[j * 140 + t + 7] = v;
    }
    __syncthreads();

    int warp = tid >> 5, lane = tid & 31;
    int t0 = warp * 16;

    if (lane < VV) {
        u64 acc[8];
#pragma unroll
        for (int p = 0; p < 8; p++) acc[p] = 0ULL;

        const float* wbase = Ws + lane;

        for (int j = 0; j < VV; j++) {
            const float* xT = &xsT[j * 140 + t0];
            const float* xS = &xsS[j * 140 + t0];
            const float* wrow = wbase + (j * TS) * VV;

            // ---- half 1: accs 0..3, window pe[0..7]/po[0..7] ----
            {
                u64 we[8], wo[8];
                const ulonglong2* pe4 = reinterpret_cast<const ulonglong2*>(xT);
                const ulonglong2* po4 = reinterpret_cast<const ulonglong2*>(xS);
#pragma unroll
                for (int q = 0; q < 4; q++) {
                    ulonglong2 ve = pe4[q]; we[2 * q] = ve.x; we[2 * q + 1] = ve.y;
                    ulonglong2 vo = po4[q]; wo[2 * q] = vo.x; wo[2 * q + 1] = vo.y;
                }
#pragma unroll
                for (int k = 0; k < TS; k++) {
                    float w = wrow[k * VV];
                    u64 w2 = pack2(w, w);
                    const u64* pr = (k & 1) ? &wo[(k - 1) >> 1] : &we[k >> 1];
#pragma unroll
                    for (int p = 0; p < 4; p++) ffma2(acc[p], pr[p], w2);
                }
            }
            // ---- half 2: accs 4..7, window pe[4..11]/po[4..11] ----
            {
                u64 we[8], wo[8];
                const ulonglong2* pe4 = reinterpret_cast<const ulonglong2*>(xT + 8);
                const ulonglong2* po4 = reinterpret_cast<const ulonglong2*>(xS + 8);
#pragma unroll
                for (int q = 0; q < 4; q++) {
                    ulonglong2 ve = pe4[q]; we[2 * q] = ve.x; we[2 * q + 1] = ve.y;
                    ulonglong2 vo = po4[q]; wo[2 * q] = vo.x; wo[2 * q + 1] = vo.y;
                }
#pragma unroll
                for (int k = 0; k < TS; k++) {
                    float w = wrow[k * VV];
                    u64 w2 = pack2(w, w);
                    const u64* pr = (k & 1) ? &wo[(k - 1) >> 1] : &we[k >> 1];
#pragma unroll
                    for (int p = 0; p < 4; p++) ffma2(acc[p + 4], pr[p], w2);
                }
            }
        }
        float* zp = g_zbuf + (size_t)(b * CC + c) * TV + lane;
#pragma unroll
        for (int p = 0; p < 8; p++) {
            zp[(t0 + 2 * p) * VV] = lo32(acc[p]);
            zp[(t0 + 2 * p + 1) * VV] = hi32(acc[p]);
        }
    }
}

// ---------------- kC: out = w3 @ z + b3, 8o x 4tv per warp, 8 warps ----------------
// Packing over o-pairs -> natural weight pairs (broadcast LDS.128 x2 per c),
// x duplicated via MOV. acc[4][4] = 32 regs -> high occupancy.
__global__ void __launch_bounds__(256, 4) kC(const float* __restrict__ w3, const float* __restrict__ b3,
                                             float* __restrict__ out) {
    int b = blockIdx.y;
    int tv0 = blockIdx.x * 128;
    int tid = threadIdx.x;
    int warp = tid >> 5, lane = tid & 31;

    __shared__ __align__(16) float zs[CC * 128];    // 32KB, [c][tv] plain
    __shared__ __align__(16) float w3T[CC * OUTC];  // 16KB, [c][o] plain

    const float* zb = g_zbuf + (size_t)b * CC * TV + tv0;
    for (int i = tid; i < CC * 32; i += 256) {
        int c = i >> 5, q = i & 31;
        *reinterpret_cast<float4*>(&zs[c * 128 + q * 4]) =
            *reinterpret_cast<const float4*>(zb + c * TV + q * 4);
    }
    for (int i = tid; i < CC * OUTC; i += 256) {
        int o = i >> 6, c = i & 63;                  // read w3 coalesced [o][c]
        w3T[c * OUTC + o] = w3[i];
    }
    __syncthreads();

    int o0 = warp * 8;
    u64 acc[4][4];   // acc[op][q] packs outputs (o0+2op, o0+2op+1) at tv = lane*4+q
#pragma unroll
    for (int op = 0; op < 4; op++) {
        u64 bp = pack2(__ldg(b3 + o0 + 2 * op), __ldg(b3 + o0 + 2 * op + 1));
#pragma unroll
        for (int q = 0; q < 4; q++) acc[op][q] = bp;
    }

    const float* zrow = &zs[lane * 4];
#pragma unroll 4
    for (int c = 0; c < CC; c++) {
        float4 xv = *reinterpret_cast<const float4*>(zrow + c * 128);   // per-lane LDS.128
        u64 xd0 = pack2(xv.x, xv.x);
        u64 xd1 = pack2(xv.y, xv.y);
        u64 xd2 = pack2(xv.z, xv.z);
        u64 xd3 = pack2(xv.w, xv.w);
        // 8 plain weights = 2 broadcast LDS.128, natural u64 pairs
        const ulonglong2* wrow = reinterpret_cast<const ulonglong2*>(&w3T[c * OUTC + o0]);
#pragma unroll
        for (int h = 0; h < 2; h++) {
            ulonglong2 wp = wrow[h];
            ffma2(acc[2 * h][0], xd0, wp.x); ffma2(acc[2 * h][1], xd1, wp.x);
            ffma2(acc[2 * h][2], xd2, wp.x); ffma2(acc[2 * h][3], xd3, wp.x);
            ffma2(acc[2 * h + 1][0], xd0, wp.y); ffma2(acc[2 * h + 1][1], xd1, wp.y);
            ffma2(acc[2 * h + 1][2], xd2, wp.y); ffma2(acc[2 * h + 1][3], xd3, wp.y);
        }
    }

    float* ob = out + (size_t)b * OUTC * TV + tv0 + lane * 4;
#pragma unroll
    for (int op = 0; op < 4; op++) {
        float4 lo, hi;
        lo.x = lo32(acc[op][0]); lo.y = lo32(acc[op][1]);
        lo.z = lo32(acc[op][2]); lo.w = lo32(acc[op][3]);
        hi.x = hi32(acc[op][0]); hi.y = hi32(acc[op][1]);
        hi.z = hi32(acc[op][2]); hi.w = hi32(acc[op][3]);
        *reinterpret_cast<float4*>(ob + (size_t)(o0 + 2 * op) * TV) = lo;
        *reinterpret_cast<float4*>(ob + (size_t)(o0 + 2 * op + 1) * TV) = hi;
    }
}

extern "C" void kernel_launch(void* const* d_in, const int* in_sizes, int n_in,
                              void* d_out, int out_size) {
    const float* x  = (const float*)d_in[0];
    const float* A  = (const float*)d_in[1];
    const float* w1 = (const float*)d_in[2];
    const float* b1 = (const float*)d_in[3];
    const float* w2 = (const float*)d_in[4];
    const float* b2 = (const float*)d_in[5];
    const float* w3 = (const float*)d_in[6];
    const float* b3 = (const float*)d_in[7];
    const float* w4 = (const float*)d_in[8];
    const float* b4 = (const float*)d_in[9];
    float* out = (float*)d_out;

    kA1<<<dim3(CC, BB), 128>>>(x);
    kA2<<<dim3(RR, BB), 128>>>(w1, b1, w2, b2);
    kB<<<dim3(CC, BB), 256>>>(x, A, w4, b4);
    kC<<<dim3(TV / 128, BB), 256>>>(w3, b3, out);
}

// round 12
// speedup vs baseline: 1.1002x; 1.0840x over previous
#include <cuda_runtime.h>
#include <cuda_bf16.h>
#include <math.h>
#include <stdint.h>

#define BB 32
#define CC 64
#define TT_ 128
#define VV 25
#define RR 8
#define TS 9
#define OUTC 64
#define TV 3200   // TT_*VV

typedef unsigned long long u64;

// scratch (allocation-free rule: device globals)
__device__ float g_xm[BB * CC * VV];                 // mean_t x
__device__ float g_dbuf[BB * RR * VV * VV];          // d[b,r,j,i]
__device__ float g_zbuf[(size_t)BB * CC * TT_ * VV]; // z[b,c,t,i]

__device__ __forceinline__ u64 pack2(float lo, float hi) {
    u64 r;
    asm("mov.b64 %0, {%1, %2};" : "=l"(r) : "f"(lo), "f"(hi));
    return r;
}
__device__ __forceinline__ void ffma2(u64& d, u64 a, u64 b) {
    asm("fma.rn.f32x2 %0, %1, %2, %0;" : "+l"(d) : "l"(a), "l"(b));
}
__device__ __forceinline__ float lo32(u64 v) { float a,b; asm("mov.b64 {%0,%1}, %2;" : "=f"(a), "=f"(b) : "l"(v)); return a; }
__device__ __forceinline__ float hi32(u64 v) { float a,b; asm("mov.b64 {%0,%1}, %2;" : "=f"(a), "=f"(b) : "l"(v)); return b; }

__device__ __forceinline__ uint32_t smem_to_u32(const void* smem_ptr) {
    uint32_t addr;
    asm("{ .reg .u64 tmp; cvta.to.shared.u64 tmp, %1; cvt.u32.u64 %0, tmp; }" : "=r"(addr) : "l"(smem_ptr));
    return addr;
}
#define SMEM_SWIZZLE_128B(byte_offset) ((byte_offset) ^ (((byte_offset) >> 3) & 0x70))

__device__ __forceinline__ void ldsm_x4(uint32_t* r, uint32_t addr) {
    asm volatile("ldmatrix.sync.aligned.m8n8.x4.shared.b16 {%0,%1,%2,%3}, [%4];"
                 : "=r"(r[0]), "=r"(r[1]), "=r"(r[2]), "=r"(r[3]) : "r"(addr));
}
// D(f32) += A(bf16 16x16) * B(bf16 16x8), row.col
__device__ __forceinline__ void mma_16816(float* d, const uint32_t* a, uint32_t b0, uint32_t b1) {
    asm volatile(
        "mma.sync.aligned.m16n8k16.row.col.f32.bf16.bf16.f32 "
        "{%0,%1,%2,%3}, {%4,%5,%6,%7}, {%8,%9}, {%0,%1,%2,%3};"
        : "+f"(d[0]), "+f"(d[1]), "+f"(d[2]), "+f"(d[3])
        : "r"(a[0]), "r"(a[1]), "r"(a[2]), "r"(a[3]), "r"(b0), "r"(b1));
}

// ---------------- kA1: coalesced mean over T, one block per (b,c) ----------------
__global__ void __launch_bounds__(128) kA1(const float* __restrict__ x) {
    int c = blockIdx.x, b = blockIdx.y;
    int tid = threadIdx.x;
    __shared__ float xt[TT_ * VV];
    __shared__ float part[VV * 4];

    const float* xp = x + (size_t)(b * CC + c) * TV;
    for (int i = tid; i < TT_ * VV; i += 128) xt[i] = xp[i];
    __syncthreads();

    if (tid < VV * 4) {
        int v = tid >> 2, s = tid & 3;
        float acc = 0.f;
#pragma unroll 8
        for (int t = s; t < TT_; t += 4) acc += xt[t * VV + v];
        part[tid] = acc;
    }
    __syncthreads();
    if (tid < VV) {
        float m = (part[tid * 4] + part[tid * 4 + 1] + part[tid * 4 + 2] + part[tid * 4 + 3]) * (1.f / (float)TT_);
        g_xm[(b * CC + c) * VV + tid] = m;
    }
}

// ---------------- kA2: x1/x2 + d = tanh(x1-x2), one block per (r, b) ----------------
__global__ void __launch_bounds__(128) kA2(const float* __restrict__ w1, const float* __restrict__ b1,
                                           const float* __restrict__ w2, const float* __restrict__ b2) {
    int r = blockIdx.x;
    int b = blockIdx.y;
    int tid = threadIdx.x;
    __shared__ float xm[CC * VV];
    __shared__ float x1s[VV];
    __shared__ float x2s[VV];

    const float* xmg = g_xm + b * (CC * VV);
    for (int i = tid; i < CC * VV; i += 128) xm[i] = xmg[i];
    __syncthreads();

    if (tid < 2 * VV) {
        int which = tid / VV;
        int v = tid % VV;
        const float* w = which ? w2 : w1;
        float s = 0.f;
#pragma unroll 8
        for (int c = 0; c < CC; c++) s = fmaf(w[r * CC + c], xm[c * VV + v], s);
        s += (which ? b2 : b1)[r];
        (which ? x2s : x1s)[v] = s;
    }
    __syncthreads();

    float* db = g_dbuf + (b * RR + r) * (VV * VV);
    for (int p = tid; p < VV * VV; p += 128) {
        int j = p / VV, i = p % VV;
        db[p] = tanhf(x1s[j] - x2s[i]);
    }
}

// ---------------- kB: dynamic conv (frozen from R10) ----------------
__global__ void __launch_bounds__(256, 4) kB(const float* __restrict__ x,
                                             const float* __restrict__ A,
                                             const float* __restrict__ w4, const float* __restrict__ b4) {
    int c = blockIdx.x;
    int b = blockIdx.y;
    int tid = threadIdx.x;

    __shared__ __align__(16) float Ws[VV * TS * VV];
    __shared__ __align__(16) float xsT[VV * 140];
    __shared__ __align__(16) float xsS[VV * 140];

    const float* db = g_dbuf + b * (RR * VV * VV);

    for (int p = tid; p < VV * VV; p += 256) {
        float dr[RR];
#pragma unroll
        for (int r = 0; r < RR; r++) dr[r] = __ldg(db + r * (VV * VV) + p);
        float a = __ldg(A + p);
        int j = p / VV, i = p % VV;
#pragma unroll
        for (int k = 0; k < TS; k++) {
            int o = c * TS + k;
            float s = a + __ldg(b4 + o);
#pragma unroll
            for (int r = 0; r < RR; r++) s = fmaf(__ldg(w4 + o * RR + r), dr[r], s);
            Ws[(j * TS + k) * VV + i] = s;
        }
    }

    for (int idx = tid; idx < VV * 8; idx += 256) {
        int j = idx / 8, s0 = idx % 8;
        xsT[j * 140 + s0] = 0.f;
        if (s0 < 7) xsS[j * 140 + s0] = 0.f;
        if (s0 == 0) {
            xsS[j * 140 + 135] = 0.f;
#pragma unroll
            for (int q = 136; q < 140; q++) { xsT[j * 140 + q] = 0.f; xsS[j * 140 + q] = 0.f; }
        }
    }
    const float* xp = x + (size_t)(b * CC + c) * TV;
    for (int idx = tid; idx < TT_ * VV; idx += 256) {
        int t = idx / VV, j = idx % VV;
        float v = xp[idx];
        xsT[j * 140 + t + 8] = v;
        xsS[j * 140 + t + 7] = v;
    }
    __syncthreads();

    int warp = tid >> 5, lane = tid & 31;
    int t0 = warp * 16;

    if (lane < VV) {
        u64 acc[8];
#pragma unroll
        for (int p = 0; p < 8; p++) acc[p] = 0ULL;

        const float* wbase = Ws + lane;

        for (int j = 0; j < VV; j++) {
            const float* xT = &xsT[j * 140 + t0];
            const float* xS = &xsS[j * 140 + t0];
            const float* wrow = wbase + (j * TS) * VV;
            {
                u64 we[8], wo[8];
                const ulonglong2* pe4 = reinterpret_cast<const ulonglong2*>(xT);
                const ulonglong2* po4 = reinterpret_cast<const ulonglong2*>(xS);
#pragma unroll
                for (int q = 0; q < 4; q++) {
                    ulonglong2 ve = pe4[q]; we[2 * q] = ve.x; we[2 * q + 1] = ve.y;
                    ulonglong2 vo = po4[q]; wo[2 * q] = vo.x; wo[2 * q + 1] = vo.y;
                }
#pragma unroll
                for (int k = 0; k < TS; k++) {
                    float w = wrow[k * VV];
                    u64 w2 = pack2(w, w);
                    const u64* pr = (k & 1) ? &wo[(k - 1) >> 1] : &we[k >> 1];
#pragma unroll
                    for (int p = 0; p < 4; p++) ffma2(acc[p], pr[p], w2);
                }
            }
            {
                u64 we[8], wo[8];
                const ulonglong2* pe4 = reinterpret_cast<const ulonglong2*>(xT + 8);
                const ulonglong2* po4 = reinterpret_cast<const ulonglong2*>(xS + 8);
#pragma unroll
                for (int q = 0; q < 4; q++) {
                    ulonglong2 ve = pe4[q]; we[2 * q] = ve.x; we[2 * q + 1] = ve.y;
                    ulonglong2 vo = po4[q]; wo[2 * q] = vo.x; wo[2 * q + 1] = vo.y;
                }
#pragma unroll
                for (int k = 0; k < TS; k++) {
                    float w = wrow[k * VV];
                    u64 w2 = pack2(w, w);
                    const u64* pr = (k & 1) ? &wo[(k - 1) >> 1] : &we[k >> 1];
#pragma unroll
                    for (int p = 0; p < 4; p++) ffma2(acc[p + 4], pr[p], w2);
                }
            }
        }
        float* zp = g_zbuf + (size_t)(b * CC + c) * TV + lane;
#pragma unroll
        for (int p = 0; p < 8; p++) {
            zp[(t0 + 2 * p) * VV] = lo32(acc[p]);
            zp[(t0 + 2 * p + 1) * VV] = hi32(acc[p]);
        }
    }
}

// ---------------- kC_mma: out^T(tv,o) = z^T(tv,c) @ w3(o,c)^T via mma.sync bf16 split ----
// Block: 256 threads (8 warps), one (128-tv tile, b). Warp w owns tv rows [w*16, w*16+16), all 64 o.
// A = z^T [128 tv][64 c] bf16 hi/lo (SW128 swizzle). B = w3 [64 o][64 c] bf16 hi/lo (SW128).
// B in [n][k] rows == col-major B -> plain ldmatrix gives the m16n8k16 B fragment.
// D = Ah*Bh + Ah*Bl + Al*Bh (f32 accum). Split-bf16 rel err ~1e-5.
__global__ void __launch_bounds__(256) kC_mma(const float* __restrict__ w3,
                                              const float* __restrict__ b3,
                                              float* __restrict__ out) {
    // static smem: 48.5KB
    __shared__ __align__(1024) char As_h[128 * 128];   // 16KB bf16 [tv][c]
    __shared__ __align__(1024) char As_l[128 * 128];   // 16KB
    __shared__ __align__(1024) char Bs_h[64 * 128];    // 8KB  bf16 [o][c]
    __shared__ __align__(1024) char Bs_l[64 * 128];    // 8KB
    __shared__ float bias_s[OUTC];

    int b = blockIdx.y;
    int tv0 = blockIdx.x * 128;
    int tid = threadIdx.x;
    int warp = tid >> 5, lane = tid & 31;

    // ---- stage A = z^T hi/lo, bf16x2-packed, SW128-swizzled ----
    const float* zb = g_zbuf + (size_t)b * CC * TV + tv0;
    {
        int tv = tid & 127;
        int mbase = (tid >> 7) * 16;    // threads 0-127: m 0..15; 128-255: m 16..31
#pragma unroll 4
        for (int mi = 0; mi < 16; mi++) {
            int m = mbase + mi;          // c-pair (2m, 2m+1)
            float v0 = zb[(size_t)(2 * m) * TV + tv];
            float v1 = zb[(size_t)(2 * m + 1) * TV + tv];
            __nv_bfloat16 h0 = __float2bfloat16(v0);
            __nv_bfloat16 h1 = __float2bfloat16(v1);
            __nv_bfloat16 l0 = __float2bfloat16(v0 - __bfloat162float(h0));
            __nv_bfloat16 l1 = __float2bfloat16(v1 - __bfloat162float(h1));
            uint32_t hp = ((uint32_t)__bfloat16_as_ushort(h1) << 16) | __bfloat16_as_ushort(h0);
            uint32_t lp = ((uint32_t)__bfloat16_as_ushort(l1) << 16) | __bfloat16_as_ushort(l0);
            uint32_t off = (uint32_t)tv * 128u + (uint32_t)m * 4u;
            uint32_t sw = SMEM_SWIZZLE_128B(off);
            *reinterpret_cast<uint32_t*>(As_h + sw) = hp;
            *reinterpret_cast<uint32_t*>(As_l + sw) = lp;
        }
    }
    // ---- stage B = w3 hi/lo ----
    for (int e = tid; e < OUTC * CC; e += 256) {
        int o = e >> 6, c = e & 63;
        float v = w3[e];
        __nv_bfloat16 h = __float2bfloat16(v);
        __nv_bfloat16 l = __float2bfloat16(v - __bfloat162float(h));
        uint32_t sw = SMEM_SWIZZLE_128B((uint32_t)o * 128u + (uint32_t)c * 2u);
        *reinterpret_cast<__nv_bfloat16*>(Bs_h + sw) = h;
        *reinterpret_cast<__nv_bfloat16*>(Bs_l + sw) = l;
    }
    if (tid < OUTC) bias_s[tid] = b3[tid];
    __syncthreads();

    uint32_t aH = smem_to_u32(As_h), aL = smem_to_u32(As_l);
    uint32_t bH = smem_to_u32(Bs_h), bL = smem_to_u32(Bs_l);

    float acc[8][4];   // 8 n-tiles (8 o each) x 4 f32 frag regs
#pragma unroll
    for (int n = 0; n < 8; n++)
#pragma unroll
        for (int q = 0; q < 4; q++) acc[n][q] = 0.f;

    int tvw = warp * 16;
    // A ldmatrix address: row tvw + (lane&15), k-byte (lane>>4)*16 within kstep
    uint32_t arow = (uint32_t)(tvw + (lane & 15)) * 128u + (uint32_t)((lane >> 4) & 1) * 16u;
    // B ldmatrix address: tile t=lane>>3: o = (t>>1)*8 + (lane&7), k-byte (t&1)*16
    uint32_t brow = (uint32_t)(((lane >> 4) & 1) * 8 + (lane & 7)) * 128u + (uint32_t)((lane >> 3) & 1) * 16u;

#pragma unroll
    for (int ks = 0; ks < 4; ks++) {
        uint32_t ah[4], al[4];
        uint32_t aoff = SMEM_SWIZZLE_128B(arow + (uint32_t)ks * 32u);
        ldsm_x4(ah, aH + aoff);
        ldsm_x4(al, aL + aoff);
#pragma unroll
        for (int np = 0; np < 4; np++) {   // n-pair: 2 n-tiles = 16 o
            uint32_t bh[4], bl[4];
            uint32_t boff = SMEM_SWIZZLE_128B(brow + (uint32_t)np * 16u * 128u + (uint32_t)ks * 32u);
            ldsm_x4(bh, bH + boff);
            ldsm_x4(bl, bL + boff);
            // regs: bh[0],bh[1] = n-tile 2np (k 0-7, 8-15); bh[2],bh[3] = n-tile 2np+1
            mma_16816(acc[2 * np],     ah, bh[0], bh[1]);
            mma_16816(acc[2 * np],     ah, bl[0], bl[1]);
            mma_16816(acc[2 * np],     al, bh[0], bh[1]);
            mma_16816(acc[2 * np + 1], ah, bh[2], bh[3]);
            mma_16816(acc[2 * np + 1], ah, bl[2], bl[3]);
            mma_16816(acc[2 * np + 1], al, bh[2], bh[3]);
        }
    }

    // ---- epilogue: D frag -> out[o][tv], + bias ----
    // lane: rows tv = tvw + lane/4 (+8), cols o = n*8 + 2*(lane&3) (+1)
    int tr = lane >> 2, cq = (lane & 3) * 2;
    float* ob = out + (size_t)b * OUTC * TV + tv0;
    int tvl = tvw + tr;
#pragma unroll
    for (int n = 0; n < 8; n++) {
        int o0 = n * 8 + cq;
        float bz0 = bias_s[o0], bz1 = bias_s[o0 + 1];
        ob[(size_t)o0 * TV + tvl]            = acc[n][0] + bz0;
        ob[(size_t)(o0 + 1) * TV + tvl]      = acc[n][1] + bz1;
        ob[(size_t)o0 * TV + tvl + 8]        = acc[n][2] + bz0;
        ob[(size_t)(o0 + 1) * TV + tvl + 8]  = acc[n][3] + bz1;
    }
}

extern "C" void kernel_launch(void* const* d_in, const int* in_sizes, int n_in,
                              void* d_out, int out_size) {
    const float* x  = (const float*)d_in[0];
    const float* A  = (const float*)d_in[1];
    const float* w1 = (const float*)d_in[2];
    const float* b1 = (const float*)d_in[3];
    const float* w2 = (const float*)d_in[4];
    const float* b2 = (const float*)d_in[5];
    const float* w3 = (const float*)d_in[6];
    const float* b3 = (const float*)d_in[7];
    const float* w4 = (const float*)d_in[8];
    const float* b4 = (const float*)d_in[9];
    float* out = (float*)d_out;

    kA1<<<dim3(CC, BB), 128>>>(x);
    kA2<<<dim3(RR, BB), 128>>>(w1, b1, w2, b2);
    kB<<<dim3(CC, BB), 256>>>(x, A, w4, b4);
    kC_mma<<<dim3(TV / 128, BB), 256>>>(w3, b3, out);
}

// round 13
// speedup vs baseline: 1.4660x; 1.3325x over previous
#include <cuda_runtime.h>
#include <cuda_bf16.h>
#include <math.h>
#include <stdint.h>

#define BB 32
#define CC 64
#define TT_ 128
#define VV 25
#define RR 8
#define TS 9
#define OUTC 64
#define TV 3200   // TT_*VV

typedef unsigned long long u64;

// scratch (allocation-free rule: device globals)
__device__ float g_xm[BB * CC * VV];                 // mean_t x
__device__ float g_dbuf[BB * RR * VV * VV];          // d[b,r,j,i]
__device__ float g_zbuf[(size_t)BB * CC * TT_ * VV]; // z[b,c,t,i]

__device__ __forceinline__ uint32_t smem_to_u32(const void* smem_ptr) {
    uint32_t addr;
    asm("{ .reg .u64 tmp; cvta.to.shared.u64 tmp, %1; cvt.u32.u64 %0, tmp; }" : "=r"(addr) : "l"(smem_ptr));
    return addr;
}
#define SMEM_SWIZZLE_128B(byte_offset) ((byte_offset) ^ (((byte_offset) >> 3) & 0x70))

__device__ __forceinline__ void ldsm_x4(uint32_t* r, uint32_t addr) {
    asm volatile("ldmatrix.sync.aligned.m8n8.x4.shared.b16 {%0,%1,%2,%3}, [%4];"
                 : "=r"(r[0]), "=r"(r[1]), "=r"(r[2]), "=r"(r[3]) : "r"(addr));
}
// D(f32) += A(bf16 16x16) * B(bf16 16x8), row.col
__device__ __forceinline__ void mma_16816(float* d, const uint32_t* a, uint32_t b0, uint32_t b1) {
    asm volatile(
        "mma.sync.aligned.m16n8k16.row.col.f32.bf16.bf16.f32 "
        "{%0,%1,%2,%3}, {%4,%5,%6,%7}, {%8,%9}, {%0,%1,%2,%3};"
        : "+f"(d[0]), "+f"(d[1]), "+f"(d[2]), "+f"(d[3])
        : "r"(a[0]), "r"(a[1]), "r"(a[2]), "r"(a[3]), "r"(b0), "r"(b1));
}
__device__ __forceinline__ void bf16_split(float v, __nv_bfloat16& h, __nv_bfloat16& l) {
    h = __float2bfloat16(v);
    l = __float2bfloat16(v - __bfloat162float(h));
}

// ---------------- kA1: coalesced mean over T, one block per (b,c) ----------------
__global__ void __launch_bounds__(128) kA1(const float* __restrict__ x) {
    int c = blockIdx.x, b = blockIdx.y;
    int tid = threadIdx.x;
    __shared__ float xt[TT_ * VV];
    __shared__ float part[VV * 4];

    const float* xp = x + (size_t)(b * CC + c) * TV;
    for (int i = tid; i < TT_ * VV; i += 128) xt[i] = xp[i];
    __syncthreads();

    if (tid < VV * 4) {
        int v = tid >> 2, s = tid & 3;
        float acc = 0.f;
#pragma unroll 8
        for (int t = s; t < TT_; t += 4) acc += xt[t * VV + v];
        part[tid] = acc;
    }
    __syncthreads();
    if (tid < VV) {
        float m = (part[tid * 4] + part[tid * 4 + 1] + part[tid * 4 + 2] + part[tid * 4 + 3]) * (1.f / (float)TT_);
        g_xm[(b * CC + c) * VV + tid] = m;
    }
}

// ---------------- kA2: x1/x2 + d = tanh(x1-x2), one block per (r, b) ----------------
__global__ void __launch_bounds__(128) kA2(const float* __restrict__ w1, const float* __restrict__ b1,
                                           const float* __restrict__ w2, const float* __restrict__ b2) {
    int r = blockIdx.x;
    int b = blockIdx.y;
    int tid = threadIdx.x;
    __shared__ float xm[CC * VV];
    __shared__ float x1s[VV];
    __shared__ float x2s[VV];

    const float* xmg = g_xm + b * (CC * VV);
    for (int i = tid; i < CC * VV; i += 128) xm[i] = xmg[i];
    __syncthreads();

    if (tid < 2 * VV) {
        int which = tid / VV;
        int v = tid % VV;
        const float* w = which ? w2 : w1;
        float s = 0.f;
#pragma unroll 8
        for (int c = 0; c < CC; c++) s = fmaf(w[r * CC + c], xm[c * VV + v], s);
        s += (which ? b2 : b1)[r];
        (which ? x2s : x1s)[v] = s;
    }
    __syncthreads();

    float* db = g_dbuf + (b * RR + r) * (VV * VV);
    for (int p = tid; p < VV * VV; p += 128) {
        int j = p / VV, i = p % VV;
        db[p] = tanhf(x1s[j] - x2s[i]);
    }
}

// ---------------- kB_mma: dynamic conv via 9 shifted GEMMs on tensor cores ----------------
// One block per (c, b), 256 threads (8 warps). Warp w owns t rows [w*16, w*16+16).
// A = xpad [s][j]: 136 rows x 32 j (25 real), bf16 hi/lo, row stride 80B (conflict-free ldsm).
//   k-pass reads window rows [k, k+128) -- the causal shift is just a row offset.
// B = W [k][i][j]: 9 groups x 32 i x 32 j bf16 hi/lo, row stride 80B.
// z[t,i] = sum_k sum_j A[t+k][j] * B_k[i][j];  D = AhBh + AhBl + AlBh (f32 accum).
#define KB_A_ROW 80
#define KB_A_BYTES (136 * KB_A_ROW)           // 10880
#define KB_B_GRP (32 * KB_A_ROW)              // 2560
#define KB_B_BYTES (TS * KB_B_GRP)            // 23040
#define KB_AH 0
#define KB_AL (KB_AH + KB_A_BYTES)            // 10880
#define KB_BH (KB_AL + KB_A_BYTES)            // 21760
#define KB_BL (KB_BH + KB_B_BYTES)            // 44800
#define KB_SMEM (KB_BL + KB_B_BYTES)          // 67840

__global__ void __launch_bounds__(256) kB_mma(const float* __restrict__ x,
                                              const float* __restrict__ Amat,
                                              const float* __restrict__ w4, const float* __restrict__ b4) {
    extern __shared__ __align__(16) char sb[];
    int c = blockIdx.x;
    int b = blockIdx.y;
    int tid = threadIdx.x;
    int warp = tid >> 5, lane = tid & 31;

    // zero all smem (covers j/i padding and causal pad rows)
    {
        uint4 z4 = make_uint4(0, 0, 0, 0);
        uint4* p4 = reinterpret_cast<uint4*>(sb);
        for (int i = tid; i < KB_SMEM / 16; i += 256) p4[i] = z4;
    }
    __syncthreads();

    // ---- build W -> B tiles [k][i][j], bf16 hi/lo ----
    const float* db = g_dbuf + b * (RR * VV * VV);
    for (int p = tid; p < VV * VV; p += 256) {
        float dr[RR];
#pragma unroll
        for (int r = 0; r < RR; r++) dr[r] = __ldg(db + r * (VV * VV) + p);
        float a = __ldg(Amat + p);
        int j = p / VV, i = p % VV;
#pragma unroll
        for (int k = 0; k < TS; k++) {
            int o = c * TS + k;
            float s = a + __ldg(b4 + o);
#pragma unroll
            for (int r = 0; r < RR; r++) s = fmaf(__ldg(w4 + o * RR + r), dr[r], s);
            __nv_bfloat16 h, l; bf16_split(s, h, l);
            uint32_t off = (uint32_t)k * KB_B_GRP + (uint32_t)i * KB_A_ROW + (uint32_t)j * 2u;
            *reinterpret_cast<__nv_bfloat16*>(sb + KB_BH + off) = h;
            *reinterpret_cast<__nv_bfloat16*>(sb + KB_BL + off) = l;
        }
    }

    // ---- stage xpad: A[s=t+8][j] = x[t][j], bf16 hi/lo ----
    const float* xp = x + (size_t)(b * CC + c) * TV;
    for (int idx = tid; idx < TT_ * VV; idx += 256) {
        int t = idx / VV, j = idx % VV;
        __nv_bfloat16 h, l; bf16_split(xp[idx], h, l);
        uint32_t off = (uint32_t)(t + 8) * KB_A_ROW + (uint32_t)j * 2u;
        *reinterpret_cast<__nv_bfloat16*>(sb + KB_AH + off) = h;
        *reinterpret_cast<__nv_bfloat16*>(sb + KB_AL + off) = l;
    }
    __syncthreads();

    uint32_t aH = smem_to_u32(sb + KB_AH), aL = smem_to_u32(sb + KB_AL);
    uint32_t bH = smem_to_u32(sb + KB_BH), bL = smem_to_u32(sb + KB_BL);

    float acc[4][4];
#pragma unroll
    for (int n = 0; n < 4; n++)
#pragma unroll
        for (int q = 0; q < 4; q++) acc[n][q] = 0.f;

    int t0 = warp * 16;
    // per-lane address components (kC-proven pattern, stride 80B)
    uint32_t a_lane = (uint32_t)(lane & 15) * KB_A_ROW + (uint32_t)((lane >> 4) & 1) * 16u;
    uint32_t b_lane = (uint32_t)(((lane >> 4) & 1) * 8 + (lane & 7)) * KB_A_ROW
                    + (uint32_t)((lane >> 3) & 1) * 16u;

#pragma unroll
    for (int k = 0; k < TS; k++) {
        uint32_t a_base = (uint32_t)(k + t0) * KB_A_ROW + a_lane;
        uint32_t b_base = (uint32_t)k * KB_B_GRP + b_lane;
#pragma unroll
        for (int ks = 0; ks < 2; ks++) {
            uint32_t ah[4], al[4];
            uint32_t aoff = a_base + (uint32_t)ks * 32u;
            ldsm_x4(ah, aH + aoff);
            ldsm_x4(al, aL + aoff);
#pragma unroll
            for (int np = 0; np < 2; np++) {
                uint32_t bh[4], bl[4];
                uint32_t boff = b_base + (uint32_t)np * 16u * KB_A_ROW + (uint32_t)ks * 32u;
                ldsm_x4(bh, bH + boff);
                ldsm_x4(bl, bL + boff);
                mma_16816(acc[2 * np],     ah, bh[0], bh[1]);
                mma_16816(acc[2 * np],     ah, bl[0], bl[1]);
                mma_16816(acc[2 * np],     al, bh[0], bh[1]);
                mma_16816(acc[2 * np + 1], ah, bh[2], bh[3]);
                mma_16816(acc[2 * np + 1], ah, bl[2], bl[3]);
                mma_16816(acc[2 * np + 1], al, bh[2], bh[3]);
            }
        }
    }

    // ---- epilogue: D frag -> z[t][i] (i < 25 only) ----
    int tr = lane >> 2, cq = (lane & 3) * 2;
    float* zp = g_zbuf + (size_t)(b * CC + c) * TV;
    int ta = t0 + tr, tb2 = t0 + tr + 8;
#pragma unroll
    for (int n = 0; n < 4; n++) {
        int i0 = n * 8 + cq;
        if (i0 < VV) {
            zp[(size_t)ta * VV + i0]  = acc[n][0];
            zp[(size_t)tb2 * VV + i0] = acc[n][2];
        }
        if (i0 + 1 < VV) {
            zp[(size_t)ta * VV + i0 + 1]  = acc[n][1];
            zp[(size_t)tb2 * VV + i0 + 1] = acc[n][3];
        }
    }
}

// ---------------- kC_mma: out^T(tv,o) = z^T(tv,c) @ w3(o,c)^T (frozen from R12) ----------------
__global__ void __launch_bounds__(256) kC_mma(const float* __restrict__ w3,
                                              const float* __restrict__ b3,
                                              float* __restrict__ out) {
    __shared__ __align__(1024) char As_h[128 * 128];
    __shared__ __align__(1024) char As_l[128 * 128];
    __shared__ __align__(1024) char Bs_h[64 * 128];
    __shared__ __align__(1024) char Bs_l[64 * 128];
    __shared__ float bias_s[OUTC];

    int b = blockIdx.y;
    int tv0 = blockIdx.x * 128;
    int tid = threadIdx.x;
    int warp = tid >> 5, lane = tid & 31;

    const float* zb = g_zbuf + (size_t)b * CC * TV + tv0;
    {
        int tv = tid & 127;
        int mbase = (tid >> 7) * 16;
#pragma unroll 4
        for (int mi = 0; mi < 16; mi++) {
            int m = mbase + mi;
            float v0 = zb[(size_t)(2 * m) * TV + tv];
            float v1 = zb[(size_t)(2 * m + 1) * TV + tv];
            __nv_bfloat16 h0, l0, h1, l1;
            bf16_split(v0, h0, l0);
            bf16_split(v1, h1, l1);
            uint32_t hp = ((uint32_t)__bfloat16_as_ushort(h1) << 16) | __bfloat16_as_ushort(h0);
            uint32_t lp = ((uint32_t)__bfloat16_as_ushort(l1) << 16) | __bfloat16_as_ushort(l0);
            uint32_t sw = SMEM_SWIZZLE_128B((uint32_t)tv * 128u + (uint32_t)m * 4u);
            *reinterpret_cast<uint32_t*>(As_h + sw) = hp;
            *reinterpret_cast<uint32_t*>(As_l + sw) = lp;
        }
    }
    for (int e = tid; e < OUTC * CC; e += 256) {
        int o = e >> 6, c = e & 63;
        __nv_bfloat16 h, l; bf16_split(w3[e], h, l);
        uint32_t sw = SMEM_SWIZZLE_128B((uint32_t)o * 128u + (uint32_t)c * 2u);
        *reinterpret_cast<__nv_bfloat16*>(Bs_h + sw) = h;
        *reinterpret_cast<__nv_bfloat16*>(Bs_l + sw) = l;
    }
    if (tid < OUTC) bias_s[tid] = b3[tid];
    __syncthreads();

    uint32_t aH = smem_to_u32(As_h), aL = smem_to_u32(As_l);
    uint32_t bH = smem_to_u32(Bs_h), bL = smem_to_u32(Bs_l);

    float acc[8][4];
#pragma unroll
    for (int n = 0; n < 8; n++)
#pragma unroll
        for (int q = 0; q < 4; q++) acc[n][q] = 0.f;

    int tvw = warp * 16;
    uint32_t arow = (uint32_t)(tvw + (lane & 15)) * 128u + (uint32_t)((lane >> 4) & 1) * 16u;
    uint32_t brow = (uint32_t)(((lane >> 4) & 1) * 8 + (lane & 7)) * 128u + (uint32_t)((lane >> 3) & 1) * 16u;

#pragma unroll
    for (int ks = 0; ks < 4; ks++) {
        uint32_t ah[4], al[4];
        uint32_t aoff = SMEM_SWIZZLE_128B(arow + (uint32_t)ks * 32u);
        ldsm_x4(ah, aH + aoff);
        ldsm_x4(al, aL + aoff);
#pragma unroll
        for (int np = 0; np < 4; np++) {
            uint32_t bh[4], bl[4];
            uint32_t boff = SMEM_SWIZZLE_128B(brow + (uint32_t)np * 16u * 128u + (uint32_t)ks * 32u);
            ldsm_x4(bh, bH + boff);
            ldsm_x4(bl, bL + boff);
            mma_16816(acc[2 * np],     ah, bh[0], bh[1]);
            mma_16816(acc[2 * np],     ah, bl[0], bl[1]);
            mma_16816(acc[2 * np],     al, bh[0], bh[1]);
            mma_16816(acc[2 * np + 1], ah, bh[2], bh[3]);
            mma_16816(acc[2 * np + 1], ah, bl[2], bl[3]);
            mma_16816(acc[2 * np + 1], al, bh[2], bh[3]);
        }
    }

    int tr = lane >> 2, cq = (lane & 3) * 2;
    float* ob = out + (size_t)b * OUTC * TV + tv0;
    int tvl = tvw + tr;
#pragma unroll
    for (int n = 0; n < 8; n++) {
        int o0 = n * 8 + cq;
        float bz0 = bias_s[o0], bz1 = bias_s[o0 + 1];
        ob[(size_t)o0 * TV + tvl]            = acc[n][0] + bz0;
        ob[(size_t)(o0 + 1) * TV + tvl]      = acc[n][1] + bz1;
        ob[(size_t)o0 * TV + tvl + 8]        = acc[n][2] + bz0;
        ob[(size_t)(o0 + 1) * TV + tvl + 8]  = acc[n][3] + bz1;
    }
}

extern "C" void kernel_launch(void* const* d_in, const int* in_sizes, int n_in,
                              void* d_out, int out_size) {
    const float* x  = (const float*)d_in[0];
    const float* A  = (const float*)d_in[1];
    const float* w1 = (const float*)d_in[2];
    const float* b1 = (const float*)d_in[3];
    const float* w2 = (const float*)d_in[4];
    const float* b2 = (const float*)d_in[5];
    const float* w3 = (const float*)d_in[6];
    const float* b3 = (const float*)d_in[7];
    const float* w4 = (const float*)d_in[8];
    const float* b4 = (const float*)d_in[9];
    float* out = (float*)d_out;

    static int smem_set = 0;
    if (!smem_set) {
        cudaFuncSetAttribute(kB_mma, cudaFuncAttributeMaxDynamicSharedMemorySize, KB_SMEM);
        smem_set = 1;
    }

    kA1<<<dim3(CC, BB), 128>>>(x);
    kA2<<<dim3(RR, BB), 128>>>(w1, b1, w2, b2);
    kB_mma<<<dim3(CC, BB), 256, KB_SMEM>>>(x, A, w4, b4);
    kC_mma<<<dim3(TV / 128, BB), 256>>>(w3, b3, out);
}

// round 14
// speedup vs baseline: 1.8261x; 1.2456x over previous
#include <cuda_runtime.h>
#include <cuda_fp16.h>
#include <math.h>
#include <stdint.h>

#define BB 32
#define CC 64
#define TT_ 128
#define VV 25
#define RR 8
#define TS 9
#define OUTC 64
#define TV 3200   // TT_*VV

// scratch (allocation-free rule: device globals)
__device__ float g_xm[BB * CC * VV];                 // mean_t x
__device__ float g_dbuf[BB * RR * VV * VV];          // d[b,r,j,i]
__device__ float g_zbuf[(size_t)BB * CC * TT_ * VV]; // z[b,c,t,i]

__device__ __forceinline__ uint32_t smem_to_u32(const void* smem_ptr) {
    uint32_t addr;
    asm("{ .reg .u64 tmp; cvta.to.shared.u64 tmp, %1; cvt.u32.u64 %0, tmp; }" : "=r"(addr) : "l"(smem_ptr));
    return addr;
}
#define SMEM_SWIZZLE_128B(byte_offset) ((byte_offset) ^ (((byte_offset) >> 3) & 0x70))

__device__ __forceinline__ void ldsm_x4(uint32_t* r, uint32_t addr) {
    asm volatile("ldmatrix.sync.aligned.m8n8.x4.shared.b16 {%0,%1,%2,%3}, [%4];"
                 : "=r"(r[0]), "=r"(r[1]), "=r"(r[2]), "=r"(r[3]) : "r"(addr));
}
// D(f32) += A(f16 16x16) * B(f16 16x8), row.col — single pass
__device__ __forceinline__ void mma_16816_f16(float* d, const uint32_t* a, uint32_t b0, uint32_t b1) {
    asm volatile(
        "mma.sync.aligned.m16n8k16.row.col.f32.f16.f16.f32 "
        "{%0,%1,%2,%3}, {%4,%5,%6,%7}, {%8,%9}, {%0,%1,%2,%3};"
        : "+f"(d[0]), "+f"(d[1]), "+f"(d[2]), "+f"(d[3])
        : "r"(a[0]), "r"(a[1]), "r"(a[2]), "r"(a[3]), "r"(b0), "r"(b1));
}
__device__ __forceinline__ uint32_t pack_h2(float a, float b) {
    __half2 h = __floats2half2_rn(a, b);
    return *reinterpret_cast<uint32_t*>(&h);
}

// ---------------- kA1: coalesced mean over T, one block per (b,c) ----------------
__global__ void __launch_bounds__(128) kA1(const float* __restrict__ x) {
    int c = blockIdx.x, b = blockIdx.y;
    int tid = threadIdx.x;
    __shared__ float xt[TT_ * VV];
    __shared__ float part[VV * 4];

    const float* xp = x + (size_t)(b * CC + c) * TV;
    for (int i = tid; i < TT_ * VV; i += 128) xt[i] = xp[i];
    __syncthreads();

    if (tid < VV * 4) {
        int v = tid >> 2, s = tid & 3;
        float acc = 0.f;
#pragma unroll 8
        for (int t = s; t < TT_; t += 4) acc += xt[t * VV + v];
        part[tid] = acc;
    }
    __syncthreads();
    if (tid < VV) {
        float m = (part[tid * 4] + part[tid * 4 + 1] + part[tid * 4 + 2] + part[tid * 4 + 3]) * (1.f / (float)TT_);
        g_xm[(b * CC + c) * VV + tid] = m;
    }
}

// ---------------- kA2: x1/x2 + d = tanh(x1-x2), one block per (r, b) ----------------
__global__ void __launch_bounds__(128) kA2(const float* __restrict__ w1, const float* __restrict__ b1,
                                           const float* __restrict__ w2, const float* __restrict__ b2) {
    int r = blockIdx.x;
    int b = blockIdx.y;
    int tid = threadIdx.x;
    __shared__ float xm[CC * VV];
    __shared__ float x1s[VV];
    __shared__ float x2s[VV];

    const float* xmg = g_xm + b * (CC * VV);
    for (int i = tid; i < CC * VV; i += 128) xm[i] = xmg[i];
    __syncthreads();

    if (tid < 2 * VV) {
        int which = tid / VV;
        int v = tid % VV;
        const float* w = which ? w2 : w1;
        float s = 0.f;
#pragma unroll 8
        for (int c = 0; c < CC; c++) s = fmaf(w[r * CC + c], xm[c * VV + v], s);
        s += (which ? b2 : b1)[r];
        (which ? x2s : x1s)[v] = s;
    }
    __syncthreads();

    float* db = g_dbuf + (b * RR + r) * (VV * VV);
    for (int p = tid; p < VV * VV; p += 128) {
        int j = p / VV, i = p % VV;
        db[p] = tanhf(x1s[j] - x2s[i]);
    }
}

// ---------------- kB_mma: dynamic conv via 9 shifted GEMMs, fp16 single-pass ----------------
// One block per (c, b), 256 threads (8 warps). Warp w owns t rows [w*16, w*16+16).
// A = xpad [s][j]: 136 rows x 32 j (25 real) fp16, row stride 80B (conflict-free ldsm).
// B = W [k][i][j]: 9 x 32 x 32 fp16, row stride 80B.
// z[t,i] = sum_k sum_j A[t+k][j] * B_k[i][j]  (f32 accumulate in mma).
#define KB_A_ROW 80
#define KB_A_BYTES (136 * KB_A_ROW)           // 10880
#define KB_B_GRP (32 * KB_A_ROW)              // 2560
#define KB_B_BYTES (TS * KB_B_GRP)            // 23040

__global__ void __launch_bounds__(256) kB_mma(const float* __restrict__ x,
                                              const float* __restrict__ Amat,
                                              const float* __restrict__ w4, const float* __restrict__ b4) {
    __shared__ __align__(16) char sA[KB_A_BYTES];
    __shared__ __align__(16) char sB[KB_B_BYTES];

    int c = blockIdx.x;
    int b = blockIdx.y;
    int tid = threadIdx.x;
    int warp = tid >> 5, lane = tid & 31;

    // zero smem (covers j/i padding and causal pad rows)
    {
        uint4 z4 = make_uint4(0, 0, 0, 0);
        uint4* pa = reinterpret_cast<uint4*>(sA);
        for (int i = tid; i < KB_A_BYTES / 16; i += 256) pa[i] = z4;
        uint4* pb = reinterpret_cast<uint4*>(sB);
        for (int i = tid; i < KB_B_BYTES / 16; i += 256) pb[i] = z4;
    }
    __syncthreads();

    // ---- build W -> B tiles [k][i][j] fp16 ----
    const float* db = g_dbuf + b * (RR * VV * VV);
    for (int p = tid; p < VV * VV; p += 256) {
        float dr[RR];
#pragma unroll
        for (int r = 0; r < RR; r++) dr[r] = __ldg(db + r * (VV * VV) + p);
        float a = __ldg(Amat + p);
        int j = p / VV, i = p % VV;
#pragma unroll
        for (int k = 0; k < TS; k++) {
            int o = c * TS + k;
            float s = a + __ldg(b4 + o);
#pragma unroll
            for (int r = 0; r < RR; r++) s = fmaf(__ldg(w4 + o * RR + r), dr[r], s);
            *reinterpret_cast<__half*>(sB + (uint32_t)k * KB_B_GRP + (uint32_t)i * KB_A_ROW + (uint32_t)j * 2u) =
                __float2half_rn(s);
        }
    }

    // ---- stage xpad: A[s=t+8][j] = x[t][j] fp16 ----
    const float* xp = x + (size_t)(b * CC + c) * TV;
    for (int idx = tid; idx < TT_ * VV; idx += 256) {
        int t = idx / VV, j = idx % VV;
        *reinterpret_cast<__half*>(sA + (uint32_t)(t + 8) * KB_A_ROW + (uint32_t)j * 2u) =
            __float2half_rn(xp[idx]);
    }
    __syncthreads();

    uint32_t aH = smem_to_u32(sA);
    uint32_t bH = smem_to_u32(sB);

    float acc[4][4];
#pragma unroll
    for (int n = 0; n < 4; n++)
#pragma unroll
        for (int q = 0; q < 4; q++) acc[n][q] = 0.f;

    int t0 = warp * 16;
    uint32_t a_lane = (uint32_t)(lane & 15) * KB_A_ROW + (uint32_t)((lane >> 4) & 1) * 16u;
    uint32_t b_lane = (uint32_t)(((lane >> 4) & 1) * 8 + (lane & 7)) * KB_A_ROW
                    + (uint32_t)((lane >> 3) & 1) * 16u;

#pragma unroll
    for (int k = 0; k < TS; k++) {
        uint32_t a_base = (uint32_t)(k + t0) * KB_A_ROW + a_lane;
        uint32_t b_base = (uint32_t)k * KB_B_GRP + b_lane;
#pragma unroll
        for (int ks = 0; ks < 2; ks++) {
            uint32_t ah[4];
            ldsm_x4(ah, aH + a_base + (uint32_t)ks * 32u);
#pragma unroll
            for (int np = 0; np < 2; np++) {
                uint32_t bh[4];
                ldsm_x4(bh, bH + b_base + (uint32_t)np * 16u * KB_A_ROW + (uint32_t)ks * 32u);
                mma_16816_f16(acc[2 * np],     ah, bh[0], bh[1]);
                mma_16816_f16(acc[2 * np + 1], ah, bh[2], bh[3]);
            }
        }
    }

    // ---- epilogue: D frag -> z[t][i] (i < 25 only) ----
    int tr = lane >> 2, cq = (lane & 3) * 2;
    float* zp = g_zbuf + (size_t)(b * CC + c) * TV;
    int ta = t0 + tr, tb2 = t0 + tr + 8;
#pragma unroll
    for (int n = 0; n < 4; n++) {
        int i0 = n * 8 + cq;
        if (i0 < VV) {
            zp[(size_t)ta * VV + i0]  = acc[n][0];
            zp[(size_t)tb2 * VV + i0] = acc[n][2];
        }
        if (i0 + 1 < VV) {
            zp[(size_t)ta * VV + i0 + 1]  = acc[n][1];
            zp[(size_t)tb2 * VV + i0 + 1] = acc[n][3];
        }
    }
}

// ---------------- kC_mma: out^T(tv,o) = z^T(tv,c) @ w3(o,c)^T, fp16 single-pass ----------------
// Block: 256 threads (8 warps), one (128-tv tile, b). Warp w owns tv rows [w*16, w*16+16), all 64 o.
// A = z^T [128 tv][64 c] fp16 (SW128 swizzle, 128B rows). B = w3 [64 o][64 c] fp16 (SW128).
__global__ void __launch_bounds__(256) kC_mma(const float* __restrict__ w3,
                                              const float* __restrict__ b3,
                                              float* __restrict__ out) {
    __shared__ __align__(1024) char As[128 * 128];   // 16KB fp16 [tv][c]
    __shared__ __align__(1024) char Bs[64 * 128];    // 8KB  fp16 [o][c]
    __shared__ float bias_s[OUTC];

    int b = blockIdx.y;
    int tv0 = blockIdx.x * 128;
    int tid = threadIdx.x;
    int warp = tid >> 5, lane = tid & 31;

    // ---- stage A = z^T fp16, h2-packed, SW128-swizzled ----
    const float* zb = g_zbuf + (size_t)b * CC * TV + tv0;
    {
        int tv = tid & 127;
        int mbase = (tid >> 7) * 16;
#pragma unroll 4
        for (int mi = 0; mi < 16; mi++) {
            int m = mbase + mi;          // c-pair (2m, 2m+1)
            float v0 = zb[(size_t)(2 * m) * TV + tv];
            float v1 = zb[(size_t)(2 * m + 1) * TV + tv];
            uint32_t hp = pack_h2(v0, v1);
            uint32_t sw = SMEM_SWIZZLE_128B((uint32_t)tv * 128u + (uint32_t)m * 4u);
            *reinterpret_cast<uint32_t*>(As + sw) = hp;
        }
    }
    // ---- stage B = w3 fp16 ----
    for (int e = tid; e < OUTC * CC; e += 256) {
        int o = e >> 6, c = e & 63;
        uint32_t sw = SMEM_SWIZZLE_128B((uint32_t)o * 128u + (uint32_t)c * 2u);
        *reinterpret_cast<__half*>(Bs + sw) = __float2half_rn(w3[e]);
    }
    if (tid < OUTC) bias_s[tid] = b3[tid];
    __syncthreads();

    uint32_t aH = smem_to_u32(As);
    uint32_t bH = smem_to_u32(Bs);

    float acc[8][4];
#pragma unroll
    for (int n = 0; n < 8; n++)
#pragma unroll
        for (int q = 0; q < 4; q++) acc[n][q] = 0.f;

    int tvw = warp * 16;
    uint32_t arow = (uint32_t)(tvw + (lane & 15)) * 128u + (uint32_t)((lane >> 4) & 1) * 16u;
    uint32_t brow = (uint32_t)(((lane >> 4) & 1) * 8 + (lane & 7)) * 128u + (uint32_t)((lane >> 3) & 1) * 16u;

#pragma unroll
    for (int ks = 0; ks < 4; ks++) {
        uint32_t ah[4];
        ldsm_x4(ah, aH + SMEM_SWIZZLE_128B(arow + (uint32_t)ks * 32u));
#pragma unroll
        for (int np = 0; np < 4; np++) {
            uint32_t bh[4];
            ldsm_x4(bh, bH + SMEM_SWIZZLE_128B(brow + (uint32_t)np * 16u * 128u + (uint32_t)ks * 32u));
            mma_16816_f16(acc[2 * np],     ah, bh[0], bh[1]);
            mma_16816_f16(acc[2 * np + 1], ah, bh[2], bh[3]);
        }
    }

    // ---- epilogue: D frag -> out[o][tv], + bias ----
    int tr = lane >> 2, cq = (lane & 3) * 2;
    float* ob = out + (size_t)b * OUTC * TV + tv0;
    int tvl = tvw + tr;
#pragma unroll
    for (int n = 0; n < 8; n++) {
        int o0 = n * 8 + cq;
        float bz0 = bias_s[o0], bz1 = bias_s[o0 + 1];
        ob[(size_t)o0 * TV + tvl]            = acc[n][0] + bz0;
        ob[(size_t)(o0 + 1) * TV + tvl]      = acc[n][1] + bz1;
        ob[(size_t)o0 * TV + tvl + 8]        = acc[n][2] + bz0;
        ob[(size_t)(o0 + 1) * TV + tvl + 8]  = acc[n][3] + bz1;
    }
}

extern "C" void kernel_launch(void* const* d_in, const int* in_sizes, int n_in,
                              void* d_out, int out_size) {
    const float* x  = (const float*)d_in[0];
    const float* A  = (const float*)d_in[1];
    const float* w1 = (const float*)d_in[2];
    const float* b1 = (const float*)d_in[3];
    const float* w2 = (const float*)d_in[4];
    const float* b2 = (const float*)d_in[5];
    const float* w3 = (const float*)d_in[6];
    const float* b3 = (const float*)d_in[7];
    const float* w4 = (const float*)d_in[8];
    const float* b4 = (const float*)d_in[9];
    float* out = (float*)d_out;

    kA1<<<dim3(CC, BB), 128>>>(x);
    kA2<<<dim3(RR, BB), 128>>>(w1, b1, w2, b2);
    kB_mma<<<dim3(CC, BB), 256>>>(x, A, w4, b4);
    kC_mma<<<dim3(TV / 128, BB), 256>>>(w3, b3, out);
}

// round 15
// speedup vs baseline: 1.9625x; 1.0747x over previous
#include <cuda_runtime.h>
#include <cuda_fp16.h>
#include <math.h>
#include <stdint.h>

#define BB 32
#define CC 64
#define TT_ 128
#define VV 25
#define RR 8
#define TS 9
#define OUTC 64
#define TV 3200    // TT_*VV
#define TVP 3328   // TT_*26 (padded z row: 26 per t so half2 stores stay 4B-aligned)

// scratch (allocation-free rule: device globals)
__device__ float g_xm[BB * CC * VV];                   // mean_t x
__device__ float g_dbuf[BB * RR * VV * VV];            // d[b,r,j,i]
__device__ __half g_zh[(size_t)BB * CC * TVP];         // z[b,c,t*26+i] fp16

__device__ __forceinline__ uint32_t smem_to_u32(const void* smem_ptr) {
    uint32_t addr;
    asm("{ .reg .u64 tmp; cvta.to.shared.u64 tmp, %1; cvt.u32.u64 %0, tmp; }" : "=r"(addr) : "l"(smem_ptr));
    return addr;
}
#define SMEM_SWIZZLE_128B(byte_offset) ((byte_offset) ^ (((byte_offset) >> 3) & 0x70))

__device__ __forceinline__ void ldsm_x4(uint32_t* r, uint32_t addr) {
    asm volatile("ldmatrix.sync.aligned.m8n8.x4.shared.b16 {%0,%1,%2,%3}, [%4];"
                 : "=r"(r[0]), "=r"(r[1]), "=r"(r[2]), "=r"(r[3]) : "r"(addr));
}
// D(f32) += A(f16 16x16) * B(f16 16x8), row.col
__device__ __forceinline__ void mma_16816_f16(float* d, const uint32_t* a, uint32_t b0, uint32_t b1) {
    asm volatile(
        "mma.sync.aligned.m16n8k16.row.col.f32.f16.f16.f32 "
        "{%0,%1,%2,%3}, {%4,%5,%6,%7}, {%8,%9}, {%0,%1,%2,%3};"
        : "+f"(d[0]), "+f"(d[1]), "+f"(d[2]), "+f"(d[3])
        : "r"(a[0]), "r"(a[1]), "r"(a[2]), "r"(a[3]), "r"(b0), "r"(b1));
}
__device__ __forceinline__ uint32_t pack_h2f(float a, float b) {
    __half2 h = __floats2half2_rn(a, b);
    return *reinterpret_cast<uint32_t*>(&h);
}

// ---------------- kA1: coalesced mean over T, one block per (b,c) ----------------
__global__ void __launch_bounds__(128) kA1(const float* __restrict__ x) {
    int c = blockIdx.x, b = blockIdx.y;
    int tid = threadIdx.x;
    __shared__ float xt[TT_ * VV];
    __shared__ float part[VV * 4];

    const float* xp = x + (size_t)(b * CC + c) * TV;
    for (int i = tid; i < TT_ * VV; i += 128) xt[i] = xp[i];
    __syncthreads();

    if (tid < VV * 4) {
        int v = tid >> 2, s = tid & 3;
        float acc = 0.f;
#pragma unroll 8
        for (int t = s; t < TT_; t += 4) acc += xt[t * VV + v];
        part[tid] = acc;
    }
    __syncthreads();
    if (tid < VV) {
        float m = (part[tid * 4] + part[tid * 4 + 1] + part[tid * 4 + 2] + part[tid * 4 + 3]) * (1.f / (float)TT_);
        g_xm[(b * CC + c) * VV + tid] = m;
    }
}

// ---------------- kA2: x1/x2 + d = tanh(x1-x2), one block per (r, b) ----------------
__global__ void __launch_bounds__(128) kA2(const float* __restrict__ w1, const float* __restrict__ b1,
                                           const float* __restrict__ w2, const float* __restrict__ b2) {
    int r = blockIdx.x;
    int b = blockIdx.y;
    int tid = threadIdx.x;
    __shared__ float xm[CC * VV];
    __shared__ float x1s[VV];
    __shared__ float x2s[VV];

    const float* xmg = g_xm + b * (CC * VV);
    for (int i = tid; i < CC * VV; i += 128) xm[i] = xmg[i];
    __syncthreads();

    if (tid < 2 * VV) {
        int which = tid / VV;
        int v = tid % VV;
        const float* w = which ? w2 : w1;
        float s = 0.f;
#pragma unroll 8
        for (int c = 0; c < CC; c++) s = fmaf(w[r * CC + c], xm[c * VV + v], s);
        s += (which ? b2 : b1)[r];
        (which ? x2s : x1s)[v] = s;
    }
    __syncthreads();

    float* db = g_dbuf + (b * RR + r) * (VV * VV);
    for (int p = tid; p < VV * VV; p += 128) {
        int j = p / VV, i = p % VV;
        db[p] = tanhf(x1s[j] - x2s[i]);
    }
}

// ---------------- kB_mma: dynamic conv via 9 shifted GEMMs, fp16, z written fp16 ----------------
#define KB_A_ROW 80
#define KB_A_BYTES (136 * KB_A_ROW)           // 10880
#define KB_B_GRP (32 * KB_A_ROW)              // 2560
#define KB_B_BYTES (TS * KB_B_GRP)            // 23040

__global__ void __launch_bounds__(256) kB_mma(const float* __restrict__ x,
                                              const float* __restrict__ Amat,
                                              const float* __restrict__ w4, const float* __restrict__ b4) {
    __shared__ __align__(16) char sA[KB_A_BYTES];
    __shared__ __align__(16) char sB[KB_B_BYTES];

    int c = blockIdx.x;
    int b = blockIdx.y;
    int tid = threadIdx.x;
    int warp = tid >> 5, lane = tid & 31;

    {
        uint4 z4 = make_uint4(0, 0, 0, 0);
        uint4* pa = reinterpret_cast<uint4*>(sA);
        for (int i = tid; i < KB_A_BYTES / 16; i += 256) pa[i] = z4;
        uint4* pb = reinterpret_cast<uint4*>(sB);
        for (int i = tid; i < KB_B_BYTES / 16; i += 256) pb[i] = z4;
    }
    __syncthreads();

    // ---- build W -> B tiles [k][i][j] fp16 ----
    const float* db = g_dbuf + b * (RR * VV * VV);
    for (int p = tid; p < VV * VV; p += 256) {
        float dr[RR];
#pragma unroll
        for (int r = 0; r < RR; r++) dr[r] = __ldg(db + r * (VV * VV) + p);
        float a = __ldg(Amat + p);
        int j = p / VV, i = p % VV;
#pragma unroll
        for (int k = 0; k < TS; k++) {
            int o = c * TS + k;
            float s = a + __ldg(b4 + o);
#pragma unroll
            for (int r = 0; r < RR; r++) s = fmaf(__ldg(w4 + o * RR + r), dr[r], s);
            *reinterpret_cast<__half*>(sB + (uint32_t)k * KB_B_GRP + (uint32_t)i * KB_A_ROW + (uint32_t)j * 2u) =
                __float2half_rn(s);
        }
    }

    // ---- stage xpad: A[s=t+8][j] = x[t][j] fp16 ----
    const float* xp = x + (size_t)(b * CC + c) * TV;
    for (int idx = tid; idx < TT_ * VV; idx += 256) {
        int t = idx / VV, j = idx % VV;
        *reinterpret_cast<__half*>(sA + (uint32_t)(t + 8) * KB_A_ROW + (uint32_t)j * 2u) =
            __float2half_rn(xp[idx]);
    }
    __syncthreads();

    uint32_t aH = smem_to_u32(sA);
    uint32_t bH = smem_to_u32(sB);

    float acc[4][4];
#pragma unroll
    for (int n = 0; n < 4; n++)
#pragma unroll
        for (int q = 0; q < 4; q++) acc[n][q] = 0.f;

    int t0 = warp * 16;
    uint32_t a_lane = (uint32_t)(lane & 15) * KB_A_ROW + (uint32_t)((lane >> 4) & 1) * 16u;
    uint32_t b_lane = (uint32_t)(((lane >> 4) & 1) * 8 + (lane & 7)) * KB_A_ROW
                    + (uint32_t)((lane >> 3) & 1) * 16u;

#pragma unroll
    for (int k = 0; k < TS; k++) {
        uint32_t a_base = (uint32_t)(k + t0) * KB_A_ROW + a_lane;
        uint32_t b_base = (uint32_t)k * KB_B_GRP + b_lane;
#pragma unroll
        for (int ks = 0; ks < 2; ks++) {
            uint32_t ah[4];
            ldsm_x4(ah, aH + a_base + (uint32_t)ks * 32u);
#pragma unroll
            for (int np = 0; np < 2; np++) {
                uint32_t bh[4];
                ldsm_x4(bh, bH + b_base + (uint32_t)np * 16u * KB_A_ROW + (uint32_t)ks * 32u);
                mma_16816_f16(acc[2 * np],     ah, bh[0], bh[1]);
                mma_16816_f16(acc[2 * np + 1], ah, bh[2], bh[3]);
            }
        }
    }

    // ---- epilogue: D frag -> z fp16 [t*26 + i]; i-pairs -> aligned half2 stores ----
    int tr = lane >> 2, cq = (lane & 3) * 2;
    __half* zp = g_zh + (size_t)(b * CC + c) * TVP;
    int ta = t0 + tr, tb2 = t0 + tr + 8;
#pragma unroll
    for (int n = 0; n < 4; n++) {
        int i0 = n * 8 + cq;
        if (i0 + 1 < VV) {
            // (t*26 + i0)*2 bytes: t*26 even, i0 even -> 4B aligned
            *reinterpret_cast<uint32_t*>(zp + (size_t)ta * 26 + i0)  = pack_h2f(acc[n][0], acc[n][1]);
            *reinterpret_cast<uint32_t*>(zp + (size_t)tb2 * 26 + i0) = pack_h2f(acc[n][2], acc[n][3]);
        } else if (i0 < VV) {   // i0 == 24
            zp[(size_t)ta * 26 + i0]  = __float2half_rn(acc[n][0]);
            zp[(size_t)tb2 * 26 + i0] = __float2half_rn(acc[n][2]);
        }
    }
}

// ---------------- kC_mma: out^T(tv,o) = z^T(tv,c) @ w3(o,c)^T, fp16; z read fp16 ----------------
__global__ void __launch_bounds__(256) kC_mma(const float* __restrict__ w3,
                                              const float* __restrict__ b3,
                                              float* __restrict__ out) {
    __shared__ __align__(1024) char As[128 * 128];   // 16KB fp16 [tv][c]
    __shared__ __align__(1024) char Bs[64 * 128];    // 8KB  fp16 [o][c]
    __shared__ float bias_s[OUTC];

    int b = blockIdx.y;
    int tv0 = blockIdx.x * 128;
    int tid = threadIdx.x;
    int warp = tid >> 5, lane = tid & 31;

    // ---- stage A = z^T fp16 (already fp16 in gmem: no cvt, half the bytes) ----
    {
        int tv = tid & 127;                  // tile-local flat (t,i) index
        int tvflat = tv0 + tv;
        int t = tvflat / VV, i = tvflat % VV;
        const __half* zrow = g_zh + (size_t)b * CC * TVP + (size_t)t * 26 + i;
        int mbase = (tid >> 7) * 16;
#pragma unroll 4
        for (int mi = 0; mi < 16; mi++) {
            int m = mbase + mi;              // c-pair (2m, 2m+1)
            uint32_t h0 = __half_as_ushort(zrow[(size_t)(2 * m) * TVP]);
            uint32_t h1 = __half_as_ushort(zrow[(size_t)(2 * m + 1) * TVP]);
            uint32_t hp = (h1 << 16) | h0;
            uint32_t sw = SMEM_SWIZZLE_128B((uint32_t)tv * 128u + (uint32_t)m * 4u);
            *reinterpret_cast<uint32_t*>(As + sw) = hp;
        }
    }
    // ---- stage B = w3 fp16 ----
    for (int e = tid; e < OUTC * CC; e += 256) {
        int o = e >> 6, c = e & 63;
        uint32_t sw = SMEM_SWIZZLE_128B((uint32_t)o * 128u + (uint32_t)c * 2u);
        *reinterpret_cast<__half*>(Bs + sw) = __float2half_rn(w3[e]);
    }
    if (tid < OUTC) bias_s[tid] = b3[tid];
    __syncthreads();

    uint32_t aH = smem_to_u32(As);
    uint32_t bH = smem_to_u32(Bs);

    float acc[8][4];
#pragma unroll
    for (int n = 0; n < 8; n++)
#pragma unroll
        for (int q = 0; q < 4; q++) acc[n][q] = 0.f;

    int tvw = warp * 16;
    uint32_t arow = (uint32_t)(tvw + (lane & 15)) * 128u + (uint32_t)((lane >> 4) & 1) * 16u;
    uint32_t brow = (uint32_t)(((lane >> 4) & 1) * 8 + (lane & 7)) * 128u + (uint32_t)((lane >> 3) & 1) * 16u;

#pragma unroll
    for (int ks = 0; ks < 4; ks++) {
        uint32_t ah[4];
        ldsm_x4(ah, aH + SMEM_SWIZZLE_128B(arow + (uint32_t)ks * 32u));
#pragma unroll
        for (int np = 0; np < 4; np++) {
            uint32_t bh[4];
            ldsm_x4(bh, bH + SMEM_SWIZZLE_128B(brow + (uint32_t)np * 16u * 128u + (uint32_t)ks * 32u));
            mma_16816_f16(acc[2 * np],     ah, bh[0], bh[1]);
            mma_16816_f16(acc[2 * np + 1], ah, bh[2], bh[3]);
        }
    }

    // ---- epilogue: D frag -> out[o][tv], + bias ----
    int tr = lane >> 2, cq = (lane & 3) * 2;
    float* ob = out + (size_t)b * OUTC * TV + tv0;
    int tvl = tvw + tr;
#pragma unroll
    for (int n = 0; n < 8; n++) {
        int o0 = n * 8 + cq;
        float bz0 = bias_s[o0], bz1 = bias_s[o0 + 1];
        ob[(size_t)o0 * TV + tvl]            = acc[n][0] + bz0;
        ob[(size_t)(o0 + 1) * TV + tvl]      = acc[n][1] + bz1;
        ob[(size_t)o0 * TV + tvl + 8]        = acc[n][2] + bz0;
        ob[(size_t)(o0 + 1) * TV + tvl + 8]  = acc[n][3] + bz1;
    }
}

extern "C" void kernel_launch(void* const* d_in, const int* in_sizes, int n_in,
                              void* d_out, int out_size) {
    const float* x  = (const float*)d_in[0];
    const float* A  = (const float*)d_in[1];
    const float* w1 = (const float*)d_in[2];
    const float* b1 = (const float*)d_in[3];
    const float* w2 = (const float*)d_in[4];
    const float* b2 = (const float*)d_in[5];
    const float* w3 = (const float*)d_in[6];
    const float* b3 = (const float*)d_in[7];
    const float* w4 = (const float*)d_in[8];
    const float* b4 = (const float*)d_in[9];
    float* out = (float*)d_out;

    kA1<<<dim3(CC, BB), 128>>>(x);
    kA2<<<dim3(RR, BB), 128>>>(w1, b1, w2, b2);
    kB_mma<<<dim3(CC, BB), 256>>>(x, A, w4, b4);
    kC_mma<<<dim3(TV / 128, BB), 256>>>(w3, b3, out);
}

// round 16
// speedup vs baseline: 2.3741x; 1.2097x over previous
#include <cuda_runtime.h>
#include <cuda_fp16.h>
#include <math.h>
#include <stdint.h>

#define BB 32
#define CC 64
#define TT_ 128
#define VV 25
#define RR 8
#define TS 9
#define OUTC 64
#define TV 3200    // TT_*VV
#define TVP 3328   // TT_*26 (padded z row)

// scratch (allocation-free rule: device globals)
__device__ float g_xm[BB * CC * VV];                   // mean_t x
__device__ float g_dbuf[BB * RR * VV * VV];            // d[b,r,j,i]
__device__ __half g_zh[(size_t)BB * CC * TVP];         // z[b,c,t*26+i] fp16

__device__ __forceinline__ uint32_t smem_to_u32(const void* smem_ptr) {
    uint32_t addr;
    asm("{ .reg .u64 tmp; cvta.to.shared.u64 tmp, %1; cvt.u32.u64 %0, tmp; }" : "=r"(addr) : "l"(smem_ptr));
    return addr;
}
#define SMEM_SWIZZLE_128B(byte_offset) ((byte_offset) ^ (((byte_offset) >> 3) & 0x70))

__device__ __forceinline__ void ldsm_x4(uint32_t* r, uint32_t addr) {
    asm volatile("ldmatrix.sync.aligned.m8n8.x4.shared.b16 {%0,%1,%2,%3}, [%4];"
                 : "=r"(r[0]), "=r"(r[1]), "=r"(r[2]), "=r"(r[3]) : "r"(addr));
}
__device__ __forceinline__ void mma_16816_f16(float* d, const uint32_t* a, uint32_t b0, uint32_t b1) {
    asm volatile(
        "mma.sync.aligned.m16n8k16.row.col.f32.f16.f16.f32 "
        "{%0,%1,%2,%3}, {%4,%5,%6,%7}, {%8,%9}, {%0,%1,%2,%3};"
        : "+f"(d[0]), "+f"(d[1]), "+f"(d[2]), "+f"(d[3])
        : "r"(a[0]), "r"(a[1]), "r"(a[2]), "r"(a[3]), "r"(b0), "r"(b1));
}
__device__ __forceinline__ uint32_t pack_h2f(float a, float b) {
    __half2 h = __floats2half2_rn(a, b);
    return *reinterpret_cast<uint32_t*>(&h);
}

// ---------------- kA1: coalesced mean over T, one block per (b,c) ----------------
__global__ void __launch_bounds__(128) kA1(const float* __restrict__ x) {
    int c = blockIdx.x, b = blockIdx.y;
    int tid = threadIdx.x;
    __shared__ float xt[TT_ * VV];
    __shared__ float part[VV * 4];

    const float* xp = x + (size_t)(b * CC + c) * TV;
    for (int i = tid; i < TT_ * VV; i += 128) xt[i] = xp[i];
    __syncthreads();

    if (tid < VV * 4) {
        int v = tid >> 2, s = tid & 3;
        float acc = 0.f;
#pragma unroll 8
        for (int t = s; t < TT_; t += 4) acc += xt[t * VV + v];
        part[tid] = acc;
    }
    __syncthreads();
    if (tid < VV) {
        float m = (part[tid * 4] + part[tid * 4 + 1] + part[tid * 4 + 2] + part[tid * 4 + 3]) * (1.f / (float)TT_);
        g_xm[(b * CC + c) * VV + tid] = m;
    }
}

// ---------------- kA2: x1/x2 + d = tanh(x1-x2), one block per (r, b) ----------------
__global__ void __launch_bounds__(128) kA2(const float* __restrict__ w1, const float* __restrict__ b1,
                                           const float* __restrict__ w2, const float* __restrict__ b2) {
    int r = blockIdx.x;
    int b = blockIdx.y;
    int tid = threadIdx.x;
    __shared__ float xm[CC * VV];
    __shared__ float x1s[VV];
    __shared__ float x2s[VV];

    const float* xmg = g_xm + b * (CC * VV);
    for (int i = tid; i < CC * VV; i += 128) xm[i] = xmg[i];
    __syncthreads();

    if (tid < 2 * VV) {
        int which = tid / VV;
        int v = tid % VV;
        const float* w = which ? w2 : w1;
        float s = 0.f;
#pragma unroll 8
        for (int c = 0; c < CC; c++) s = fmaf(w[r * CC + c], xm[c * VV + v], s);
        s += (which ? b2 : b1)[r];
        (which ? x2s : x1s)[v] = s;
    }
    __syncthreads();

    float* db = g_dbuf + (b * RR + r) * (VV * VV);
    for (int p = tid; p < VV * VV; p += 128) {
        int j = p / VV, i = p % VV;
        db[p] = tanhf(x1s[j] - x2s[i]);
    }
}

// ---------------- kB_mma: dynamic conv via 9 shifted GEMMs (fp16) ----------------
// FIX R15: w4/b4 staged to smem ONCE per block (was 216 redundant LDG/thread = ~34us chip-wide LSU).
#define KB_A_ROW 80
#define KB_A_BYTES (136 * KB_A_ROW)           // 10880
#define KB_B_GRP (32 * KB_A_ROW)              // 2560
#define KB_B_BYTES (TS * KB_B_GRP)            // 23040

__global__ void __launch_bounds__(256) kB_mma(const float* __restrict__ x,
                                              const float* __restrict__ Amat,
                                              const float* __restrict__ w4, const float* __restrict__ b4) {
    __shared__ __align__(16) char sA[KB_A_BYTES];
    __shared__ __align__(16) char sB[KB_B_BYTES];
    __shared__ __align__(16) float4 w4s4[TS * 2];  // [k][half]: w4[c*9+k][0..3], [4..7]
    __shared__ float b4s[TS];

    int c = blockIdx.x;
    int b = blockIdx.y;
    int tid = threadIdx.x;
    int warp = tid >> 5, lane = tid & 31;

    // phase 0: zero smem tiles + stage w4/b4
    {
        uint4 z4 = make_uint4(0, 0, 0, 0);
        uint4* pa = reinterpret_cast<uint4*>(sA);
        for (int i = tid; i < KB_A_BYTES / 16; i += 256) pa[i] = z4;
        uint4* pb = reinterpret_cast<uint4*>(sB);
        for (int i = tid; i < KB_B_BYTES / 16; i += 256) pb[i] = z4;
    }
    if (tid < TS * 2) {
        int k = tid >> 1, h = tid & 1;
        w4s4[tid] = *reinterpret_cast<const float4*>(w4 + (size_t)(c * TS + k) * RR + h * 4);
    }
    if (tid < TS) b4s[tid] = b4[c * TS + tid];
    __syncthreads();

    // ---- build W -> B tiles [k][i][j] fp16 (w4 from smem broadcast float4) ----
    const float* db = g_dbuf + b * (RR * VV * VV);
    for (int p = tid; p < VV * VV; p += 256) {
        float dr[RR];
#pragma unroll
        for (int r = 0; r < RR; r++) dr[r] = __ldg(db + r * (VV * VV) + p);
        float a = __ldg(Amat + p);
        int j = p / VV, i = p % VV;
#pragma unroll
        for (int k = 0; k < TS; k++) {
            float4 wa = w4s4[2 * k], wb = w4s4[2 * k + 1];
            float s = a + b4s[k];
            s = fmaf(wa.x, dr[0], s); s = fmaf(wa.y, dr[1], s);
            s = fmaf(wa.z, dr[2], s); s = fmaf(wa.w, dr[3], s);
            s = fmaf(wb.x, dr[4], s); s = fmaf(wb.y, dr[5], s);
            s = fmaf(wb.z, dr[6], s); s = fmaf(wb.w, dr[7], s);
            *reinterpret_cast<__half*>(sB + (uint32_t)k * KB_B_GRP + (uint32_t)i * KB_A_ROW + (uint32_t)j * 2u) =
                __float2half_rn(s);
        }
    }

    // ---- stage xpad: A[s=t+8][j] = x[t][j] fp16 ----
    const float* xp = x + (size_t)(b * CC + c) * TV;
    for (int idx = tid; idx < TT_ * VV; idx += 256) {
        int t = idx / VV, j = idx % VV;
        *reinterpret_cast<__half*>(sA + (uint32_t)(t + 8) * KB_A_ROW + (uint32_t)j * 2u) =
            __float2half_rn(xp[idx]);
    }
    __syncthreads();

    uint32_t aH = smem_to_u32(sA);
    uint32_t bH = smem_to_u32(sB);

    float acc[4][4];
#pragma unroll
    for (int n = 0; n < 4; n++)
#pragma unroll
        for (int q = 0; q < 4; q++) acc[n][q] = 0.f;

    int t0 = warp * 16;
    uint32_t a_lane = (uint32_t)(lane & 15) * KB_A_ROW + (uint32_t)((lane >> 4) & 1) * 16u;
    uint32_t b_lane = (uint32_t)(((lane >> 4) & 1) * 8 + (lane & 7)) * KB_A_ROW
                    + (uint32_t)((lane >> 3) & 1) * 16u;

#pragma unroll
    for (int k = 0; k < TS; k++) {
        uint32_t a_base = (uint32_t)(k + t0) * KB_A_ROW + a_lane;
        uint32_t b_base = (uint32_t)k * KB_B_GRP + b_lane;
#pragma unroll
        for (int ks = 0; ks < 2; ks++) {
            uint32_t ah[4];
            ldsm_x4(ah, aH + a_base + (uint32_t)ks * 32u);
#pragma unroll
            for (int np = 0; np < 2; np++) {
                uint32_t bh[4];
                ldsm_x4(bh, bH + b_base + (uint32_t)np * 16u * KB_A_ROW + (uint32_t)ks * 32u);
                mma_16816_f16(acc[2 * np],     ah, bh[0], bh[1]);
                mma_16816_f16(acc[2 * np + 1], ah, bh[2], bh[3]);
            }
        }
    }

    // ---- epilogue: D frag -> z fp16 [t*26 + i] ----
    int tr = lane >> 2, cq = (lane & 3) * 2;
    __half* zp = g_zh + (size_t)(b * CC + c) * TVP;
    int ta = t0 + tr, tb2 = t0 + tr + 8;
#pragma unroll
    for (int n = 0; n < 4; n++) {
        int i0 = n * 8 + cq;
        if (i0 + 1 < VV) {
            *reinterpret_cast<uint32_t*>(zp + (size_t)ta * 26 + i0)  = pack_h2f(acc[n][0], acc[n][1]);
            *reinterpret_cast<uint32_t*>(zp + (size_t)tb2 * 26 + i0) = pack_h2f(acc[n][2], acc[n][3]);
        } else if (i0 < VV) {
            zp[(size_t)ta * 26 + i0]  = __float2half_rn(acc[n][0]);
            zp[(size_t)tb2 * 26 + i0] = __float2half_rn(acc[n][2]);
        }
    }
}

// ---------------- kC_mma: out^T(tv,o) = z^T(tv,c) @ w3(o,c)^T, fp16, 2 batches/block ----------------
// grid (25, 16): block handles tv-tile for b0 = by*2 and b0+1, sharing w3/bias staging.
__global__ void __launch_bounds__(256) kC_mma(const float* __restrict__ w3,
                                              const float* __restrict__ b3,
                                              float* __restrict__ out) {
    __shared__ __align__(1024) char As0[128 * 128];  // 16KB fp16 [tv][c], batch b0
    __shared__ __align__(1024) char As1[128 * 128];  // 16KB, batch b0+1
    __shared__ __align__(1024) char Bs[64 * 128];    // 8KB  fp16 [o][c]
    __shared__ float bias_s[OUTC];

    int b0 = blockIdx.y * 2;
    int tv0 = blockIdx.x * 128;
    int tid = threadIdx.x;
    int warp = tid >> 5, lane = tid & 31;

    // ---- stage A tiles (both batches; LDGs issued up-front for MLP) ----
    {
        int tv = tid & 127;
        int tvflat = tv0 + tv;
        int t = tvflat / VV, i = tvflat % VV;
        int mbase = (tid >> 7) * 16;
        const __half* zr0 = g_zh + (size_t)b0 * CC * TVP + (size_t)t * 26 + i;
        const __half* zr1 = g_zh + (size_t)(b0 + 1) * CC * TVP + (size_t)t * 26 + i;
#pragma unroll 4
        for (int mi = 0; mi < 16; mi++) {
            int m = mbase + mi;
            uint32_t sw = SMEM_SWIZZLE_128B((uint32_t)tv * 128u + (uint32_t)m * 4u);
            uint32_t a0 = __half_as_ushort(zr0[(size_t)(2 * m) * TVP]);
            uint32_t a1 = __half_as_ushort(zr0[(size_t)(2 * m + 1) * TVP]);
            uint32_t c0 = __half_as_ushort(zr1[(size_t)(2 * m) * TVP]);
            uint32_t c1 = __half_as_ushort(zr1[(size_t)(2 * m + 1) * TVP]);
            *reinterpret_cast<uint32_t*>(As0 + sw) = (a1 << 16) | a0;
            *reinterpret_cast<uint32_t*>(As1 + sw) = (c1 << 16) | c0;
        }
    }
    // ---- stage B = w3 fp16 (once for both batches) ----
    for (int e = tid; e < OUTC * CC; e += 256) {
        int o = e >> 6, c = e & 63;
        uint32_t sw = SMEM_SWIZZLE_128B((uint32_t)o * 128u + (uint32_t)c * 2u);
        *reinterpret_cast<__half*>(Bs + sw) = __float2half_rn(w3[e]);
    }
    if (tid < OUTC) bias_s[tid] = b3[tid];
    __syncthreads();

    uint32_t bH = smem_to_u32(Bs);
    int tvw = warp * 16;
    uint32_t arow = (uint32_t)(tvw + (lane & 15)) * 128u + (uint32_t)((lane >> 4) & 1) * 16u;
    uint32_t brow = (uint32_t)(((lane >> 4) & 1) * 8 + (lane & 7)) * 128u + (uint32_t)((lane >> 3) & 1) * 16u;
    int tr = lane >> 2, cq = (lane & 3) * 2;

#pragma unroll
    for (int bb = 0; bb < 2; bb++) {
        uint32_t aH = smem_to_u32(bb ? As1 : As0);

        float acc[8][4];
#pragma unroll
        for (int n = 0; n < 8; n++)
#pragma unroll
            for (int q = 0; q < 4; q++) acc[n][q] = 0.f;

#pragma unroll
        for (int ks = 0; ks < 4; ks++) {
            uint32_t ah[4];
            ldsm_x4(ah, aH + SMEM_SWIZZLE_128B(arow + (uint32_t)ks * 32u));
#pragma unroll
            for (int np = 0; np < 4; np++) {
                uint32_t bh[4];
                ldsm_x4(bh, bH + SMEM_SWIZZLE_128B(brow + (uint32_t)np * 16u * 128u + (uint32_t)ks * 32u));
                mma_16816_f16(acc[2 * np],     ah, bh[0], bh[1]);
                mma_16816_f16(acc[2 * np + 1], ah, bh[2], bh[3]);
            }
        }

        float* ob = out + (size_t)(b0 + bb) * OUTC * TV + tv0;
        int tvl = tvw + tr;
#pragma unroll
        for (int n = 0; n < 8; n++) {
            int o0 = n * 8 + cq;
            float bz0 = bias_s[o0], bz1 = bias_s[o0 + 1];
            ob[(size_t)o0 * TV + tvl]            = acc[n][0] + bz0;
            ob[(size_t)(o0 + 1) * TV + tvl]      = acc[n][1] + bz1;
            ob[(size_t)o0 * TV + tvl + 8]        = acc[n][2] + bz0;
            ob[(size_t)(o0 + 1) * TV + tvl + 8]  = acc[n][3] + bz1;
        }
    }
}

extern "C" void kernel_launch(void* const* d_in, const int* in_sizes, int n_in,
                              void* d_out, int out_size) {
    const float* x  = (const float*)d_in[0];
    const float* A  = (const float*)d_in[1];
    const float* w1 = (const float*)d_in[2];
    const float* b1 = (const float*)d_in[3];
    const float* w2 = (const float*)d_in[4];
    const float* b2 = (const float*)d_in[5];
    const float* w3 = (const float*)d_in[6];
    const float* b3 = (const float*)d_in[7];
    const float* w4 = (const float*)d_in[8];
    const float* b4 = (const float*)d_in[9];
    float* out = (float*)d_out;

    kA1<<<dim3(CC, BB), 128>>>(x);
    kA2<<<dim3(RR, BB), 128>>>(w1, b1, w2, b2);
    kB_mma<<<dim3(CC, BB), 256>>>(x, A, w4, b4);
    kC_mma<<<dim3(TV / 128, BB / 2), 256>>>(w3, b3, out);
}